// round 14
// baseline (speedup 1.0000x reference)
#include <cuda_runtime.h>
#include <cuda_fp16.h>
#include <cstdint>
#include <math.h>

// ---------------------------------------------------------------------------
// Problem constants
// ---------------------------------------------------------------------------
#define BATCH 16
#define SEQ   1024
#define DIM   768
#define HEADS 12
#define HDIM  64
#define HID   3072
#define ROWS  (BATCH*SEQ)     // 16384
#define QKVD  (3*DIM)         // 2304

// ---------------------------------------------------------------------------
// Scratch (device globals — no allocation allowed)
// ---------------------------------------------------------------------------
__device__ __half g_lnh [(size_t)ROWS * DIM];
__device__ __half g_qkvh[(size_t)ROWS * QKVD];
__device__ __half g_atth[(size_t)ROWS * DIM];
__device__ __half g_hh  [(size_t)ROWS * HID];
__device__ float  g_x1  [(size_t)ROWS * DIM];
__device__ __half g_wqkvh[(size_t)QKVD * DIM];
__device__ __half g_wouth[(size_t)DIM * DIM];
__device__ __half g_wfc1h[(size_t)HID * DIM];
__device__ __half g_wfc2h[(size_t)DIM * HID];

// ---------------------------------------------------------------------------
// Helpers
// ---------------------------------------------------------------------------
__device__ __forceinline__ uint32_t smem_u32(const void* p) {
    uint32_t a;
    asm("{ .reg .u64 t; cvta.to.shared.u64 t, %1; cvt.u32.u64 %0, t; }" : "=r"(a) : "l"(p));
    return a;
}
__device__ __forceinline__ void ldsm4(uint32_t* r, uint32_t addr) {
    asm volatile("ldmatrix.sync.aligned.m8n8.x4.shared.b16 {%0,%1,%2,%3}, [%4];"
        : "=r"(r[0]), "=r"(r[1]), "=r"(r[2]), "=r"(r[3]) : "r"(addr));
}
__device__ __forceinline__ void ldsm4t(uint32_t* r, uint32_t addr) {
    asm volatile("ldmatrix.sync.aligned.m8n8.x4.trans.shared.b16 {%0,%1,%2,%3}, [%4];"
        : "=r"(r[0]), "=r"(r[1]), "=r"(r[2]), "=r"(r[3]) : "r"(addr));
}
__device__ __forceinline__ void mma_f16(float* c, const uint32_t* a,
                                        uint32_t b0, uint32_t b1) {
    asm volatile(
        "mma.sync.aligned.m16n8k16.row.col.f32.f16.f16.f32 "
        "{%0,%1,%2,%3}, {%4,%5,%6,%7}, {%8,%9}, {%0,%1,%2,%3};"
        : "+f"(c[0]), "+f"(c[1]), "+f"(c[2]), "+f"(c[3])
        : "r"(a[0]), "r"(a[1]), "r"(a[2]), "r"(a[3]), "r"(b0), "r"(b1));
}
__device__ __forceinline__ uint32_t sw128(uint32_t off) {
    return off ^ ((off >> 3) & 0x70);
}
__device__ __forceinline__ float fexp2(float x) {
    float y; asm("ex2.approx.f32 %0, %1;" : "=f"(y) : "f"(x)); return y;
}
__device__ __forceinline__ uint32_t h2exp2_u(uint32_t x) {
    uint32_t y; asm("ex2.approx.f16x2 %0, %1;" : "=r"(y) : "r"(x)); return y;
}
#define CP_ASYNC16(dst, src) \
    asm volatile("cp.async.cg.shared.global [%0], [%1], 16;" \
                 :: "r"(dst), "l"(src) : "memory")
#define CP_COMMIT() asm volatile("cp.async.commit_group;" ::: "memory")
#define CP_WAIT1()  asm volatile("cp.async.wait_group 1;"  ::: "memory")

// ---------------------------------------------------------------------------
// fp32 -> fp16 conversion, all four weights in one launch
// ---------------------------------------------------------------------------
__global__ void f2h_all_kernel(const float* __restrict__ s0, __half* __restrict__ d0, int n0,
                               const float* __restrict__ s1, __half* __restrict__ d1, int n1,
                               const float* __restrict__ s2, __half* __restrict__ d2, int n2,
                               const float* __restrict__ s3, __half* __restrict__ d3, int n3)
{
    int i = (blockIdx.x * 256 + threadIdx.x) * 4;
    const float* s; __half* d;
    if (i < n0)                   { s = s0; d = d0; }
    else if ((i -= n0) < n1)      { s = s1; d = d1; }
    else if ((i -= n1) < n2)      { s = s2; d = d2; }
    else if ((i -= n2) < n3)      { s = s3; d = d3; }
    else return;
    float4 v = *(const float4*)(s + i);
    *(__half2*)(d + i)     = __floats2half2_rn(v.x, v.y);
    *(__half2*)(d + i + 2) = __floats2half2_rn(v.z, v.w);
}

// ---------------------------------------------------------------------------
// LayerNorm: one block per row (D=768), 192 threads x float4, half out
// ---------------------------------------------------------------------------
__global__ void __launch_bounds__(192)
ln_kernel(const float* __restrict__ x,
          const float* __restrict__ gg,
          const float* __restrict__ bb,
          __half* __restrict__ y)
{
    const int row = blockIdx.x;
    const int tid = threadIdx.x;

    const float4 v = *(const float4*)(x + (size_t)row * DIM + tid * 4);
    float s = v.x + v.y + v.z + v.w;
    float q = v.x*v.x + v.y*v.y + v.z*v.z + v.w*v.w;

    #pragma unroll
    for (int m = 16; m; m >>= 1) {
        s += __shfl_xor_sync(0xffffffffu, s, m);
        q += __shfl_xor_sync(0xffffffffu, q, m);
    }
    __shared__ float sh[12];
    const int warp = tid >> 5, lane = tid & 31;
    if (!lane) { sh[warp] = s; sh[warp + 6] = q; }
    __syncthreads();
    if (tid == 0) {
        float ts = 0.f, tq = 0.f;
        #pragma unroll
        for (int w = 0; w < 6; w++) { ts += sh[w]; tq += sh[w + 6]; }
        sh[0] = ts * (1.0f / DIM);
        sh[6] = tq * (1.0f / DIM);
    }
    __syncthreads();
    const float mean = sh[0];
    const float rstd = rsqrtf(sh[6] - mean * mean + 1e-5f);

    const float4 g4 = *(const float4*)(gg + tid * 4);
    const float4 b4 = *(const float4*)(bb + tid * 4);
    __half2 h0 = __floats2half2_rn((v.x - mean) * rstd * g4.x + b4.x,
                                   (v.y - mean) * rstd * g4.y + b4.y);
    __half2 h1 = __floats2half2_rn((v.z - mean) * rstd * g4.z + b4.z,
                                   (v.w - mean) * rstd * g4.w + b4.w);
    *(__half2*)(y + (size_t)row * DIM + tid * 4)     = h0;
    *(__half2*)(y + (size_t)row * DIM + tid * 4 + 2) = h1;
}

// ---------------------------------------------------------------------------
// fp16 mma.sync GEMM (R12 proven config, frozen).
// CTA tile 128x128, BK=64. 4 warps (2M x 2N), warp tile 64x64 (acc 128 regs).
// 128 threads, __launch_bounds__(128,2): 256-reg budget, 2 CTAs/SM.
// SMEM: 3 stages x (A 16K + B 16K) = 96KB. 2 CTAs/SM (192KB).
// EPI: 0 = bias, 1 = bias+GELU(exact), 2 = bias+residual(fp32)
// ---------------------------------------------------------------------------
template<int EPI, bool HALF_OUT>
__global__ void __launch_bounds__(128, 2)
tgemm_kernel(const __half* __restrict__ A,
             const __half* __restrict__ W,
             const float* __restrict__ bias,
             const float* __restrict__ res,
             void* __restrict__ Cv,
             int M, int N, int K)
{
    extern __shared__ char smem[];
    const uint32_t sb = smem_u32(smem);
    const int tid   = threadIdx.x;
    const int wid   = tid >> 5;
    const int lane  = tid & 31;
    const int warpM = wid & 1;
    const int warpN = wid >> 1;
    const int m0 = blockIdx.y * 128;
    const int n0 = blockIdx.x * 128;

    uint32_t aOff[4], bOff[4];
    {
        const int r8 = (lane & 7) + ((lane >> 3) & 1) * 8;
        #pragma unroll
        for (int mf = 0; mf < 4; mf++) {
            const int row = warpM * 64 + mf * 16 + r8;
            aOff[mf] = sw128((uint32_t)(row * 128 + (lane >> 4) * 16));
        }
        const int rB = (lane & 7) + ((lane >> 4) & 1) * 8;
        #pragma unroll
        for (int p = 0; p < 4; p++) {
            const int row = warpN * 64 + p * 16 + rB;
            bOff[p] = sw128((uint32_t)(row * 128 + ((lane >> 3) & 1) * 16));
        }
    }

    float acc[4][8][4];
    #pragma unroll
    for (int i = 0; i < 4; i++)
        #pragma unroll
        for (int j = 0; j < 8; j++)
            #pragma unroll
            for (int q = 0; q < 4; q++) acc[i][j][q] = 0.f;

    const int nIter = K >> 6;                 // BK = 64 halfs
    const int lr0  = tid >> 3;
    const int lch  = tid & 7;
    const uint32_t stOff = sw128((uint32_t)(lr0 * 128 + lch * 16));
    const __half* apt = A + (size_t)(m0 + lr0) * K + lch * 8;
    const __half* bpt = W + (size_t)(n0 + lr0) * K + lch * 8;

    #pragma unroll
    for (int s = 0; s < 2; s++) {
        const int k0 = s << 6;
        const uint32_t dstA = sb + (uint32_t)s * 32768u + stOff;
        #pragma unroll
        for (int g = 0; g < 8; g++)
            CP_ASYNC16(dstA + g * 2048, apt + (size_t)g * 16 * K + k0);
        #pragma unroll
        for (int g = 0; g < 8; g++)
            CP_ASYNC16(dstA + 16384 + g * 2048, bpt + (size_t)g * 16 * K + k0);
        CP_COMMIT();
    }

    int slotNext = 2;
    for (int it = 0; it < nIter; ++it) {
        CP_WAIT1();
        __syncthreads();

        if (it + 2 < nIter) {
            const int k0 = (it + 2) << 6;
            const uint32_t dstA = sb + (uint32_t)slotNext * 32768u + stOff;
            #pragma unroll
            for (int g = 0; g < 8; g++)
                CP_ASYNC16(dstA + g * 2048, apt + (size_t)g * 16 * K + k0);
            #pragma unroll
            for (int g = 0; g < 8; g++)
                CP_ASYNC16(dstA + 16384 + g * 2048, bpt + (size_t)g * 16 * K + k0);
        }
        CP_COMMIT();
        slotNext = (slotNext == 2) ? 0 : slotNext + 1;

        const uint32_t aB = sb + (uint32_t)(it % 3) * 32768u;
        const uint32_t bB = aB + 16384u;

        #pragma unroll
        for (int ks = 0; ks < 4; ks++) {
            const uint32_t kx = (uint32_t)(ks << 5);
            uint32_t af[4][4], bf[4][4];
            #pragma unroll
            for (int mf = 0; mf < 4; mf++) ldsm4(af[mf], aB + (aOff[mf] ^ kx));
            #pragma unroll
            for (int p = 0; p < 4; p++)   ldsm4(bf[p],  bB + (bOff[p]  ^ kx));
            #pragma unroll
            for (int mf = 0; mf < 4; mf++)
                #pragma unroll
                for (int nf = 0; nf < 8; nf++)
                    mma_f16(acc[mf][nf], af[mf],
                            bf[nf >> 1][(nf & 1) * 2],
                            bf[nf >> 1][(nf & 1) * 2 + 1]);
        }
    }

    #pragma unroll
    for (int mf = 0; mf < 4; mf++) {
        const int r0 = m0 + warpM * 64 + mf * 16 + (lane >> 2);
        #pragma unroll
        for (int nf = 0; nf < 8; nf++) {
            const int col = n0 + warpN * 64 + nf * 8 + (lane & 3) * 2;
            const float b0 = bias[col], b1 = bias[col + 1];
            #pragma unroll
            for (int h = 0; h < 2; h++) {
                const int r = r0 + h * 8;
                float v0 = acc[mf][nf][h * 2 + 0] + b0;
                float v1 = acc[mf][nf][h * 2 + 1] + b1;
                if (EPI == 1) {
                    v0 = 0.5f * v0 * (1.0f + erff(v0 * 0.70710678118654752f));
                    v1 = 0.5f * v1 * (1.0f + erff(v1 * 0.70710678118654752f));
                }
                if (EPI == 2) {
                    const float2 rr = *(const float2*)(res + (size_t)r * N + col);
                    v0 += rr.x; v1 += rr.y;
                }
                if (HALF_OUT) {
                    *(__half2*)((__half*)Cv + (size_t)r * N + col) =
                        __floats2half2_rn(v0, v1);
                } else {
                    *(float2*)((float*)Cv + (size_t)r * N + col) =
                        make_float2(v0, v1);
                }
            }
        }
    }
}

// ---------------------------------------------------------------------------
// fp16 tensor-core flash attention: 128 threads, 4 warps x 32 q-rows.
// Register-resident P; deferred l_i sum-reduction (moved AFTER the PV MMAs
// so the 4x26cyc shfl chains overlap with tensor work; values identical).
// cp.async double-buffered K/V; base-2 softmax via ex2.f16x2.
// SMEM: Q 16K @0 | K 2x8K @16384 | V 2x8K @32768 = 48KB. 2 CTAs/SM.
// ---------------------------------------------------------------------------
__global__ void __launch_bounds__(128, 2)
attn_kernel(const __half* __restrict__ qkv, __half* __restrict__ out)
{
    extern __shared__ char smem[];
    const uint32_t sb = smem_u32(smem);
    const uint32_t Q0 = 0u, K0 = 16384u, V0 = 32768u;

    const int b  = blockIdx.z;
    const int h  = blockIdx.y;
    const int q0 = blockIdx.x * 128;
    const int tid = threadIdx.x, wid = tid >> 5, lane = tid & 31;

    const float qs = 0.03608439182435162f * 1.4426950408889634f;

    const int krow = tid >> 3;          // 0..15 (+g*16)
    const int kch  = tid & 7;
    const uint32_t kvOff0 = sw128((uint32_t)(krow * 128 + kch * 16));

    // ---- load Q tile 128x64, pre-scaled in fp32 ----
    #pragma unroll
    for (int g = 0; g < 8; g++) {
        const int idx = tid + g * 128;
        const int row = idx >> 3, ch = idx & 7;
        const __half* qp = qkv + (size_t)(b * SEQ + q0 + row) * QKVD + h * HDIM + ch * 8;
        uint4 raw = *(const uint4*)qp;
        __half2* hp = (__half2*)&raw;
        #pragma unroll
        for (int j = 0; j < 4; j++) {
            float2 f = __half22float2(hp[j]);
            hp[j] = __floats2half2_rn(f.x * qs, f.y * qs);
        }
        *(uint4*)(smem + Q0 + sw128((uint32_t)(row * 128 + ch * 16))) = raw;
    }

    // ---- prefetch KV tile 0 ----
    {
        const __half* kp = qkv + (size_t)(b * SEQ + krow) * QKVD + DIM + h * HDIM + kch * 8;
        #pragma unroll
        for (int g = 0; g < 4; g++) {
            const __half* src = kp + (size_t)g * 16 * QKVD;
            CP_ASYNC16(sb + K0 + kvOff0 + g * 2048, src);
            CP_ASYNC16(sb + V0 + kvOff0 + g * 2048, src + DIM);
        }
        CP_COMMIT();
    }

    // ---- fragment offsets (warp owns q-rows [wid*32, wid*32+32)) ----
    uint32_t aOffQ[2], bOffK[4], bOffV[4];
    {
        const int r8 = (lane & 7) + ((lane >> 3) & 1) * 8;
        #pragma unroll
        for (int mf = 0; mf < 2; mf++)
            aOffQ[mf] = sw128((uint32_t)((wid * 32 + mf * 16 + r8) * 128
                                         + (lane >> 4) * 16));
        const int rB = (lane & 7) + ((lane >> 4) & 1) * 8;
        #pragma unroll
        for (int p = 0; p < 4; p++)
            bOffK[p] = sw128((uint32_t)((p * 16 + rB) * 128 + ((lane >> 3) & 1) * 16));
        #pragma unroll
        for (int p = 0; p < 4; p++)
            bOffV[p] = sw128((uint32_t)(r8 * 128 + p * 32 + ((lane >> 4) & 1) * 16));
    }

    float accO[2][8][4];
    #pragma unroll
    for (int i = 0; i < 2; i++)
        #pragma unroll
        for (int j = 0; j < 8; j++)
            #pragma unroll
            for (int q = 0; q < 4; q++) accO[i][j][q] = 0.f;
    float m_i[2][2] = {{-1e30f, -1e30f}, {-1e30f, -1e30f}};
    float l_i[2][2] = {{0.f, 0.f}, {0.f, 0.f}};

    for (int t = 0; t < SEQ / 64; t++) {
        if (t + 1 < SEQ / 64) {
            const uint32_t buf = (uint32_t)((t + 1) & 1) * 8192u;
            const __half* kp = qkv + (size_t)(b * SEQ + (t + 1) * 64 + krow) * QKVD
                               + DIM + h * HDIM + kch * 8;
            #pragma unroll
            for (int g = 0; g < 4; g++) {
                const __half* src = kp + (size_t)g * 16 * QKVD;
                CP_ASYNC16(sb + K0 + buf + kvOff0 + g * 2048, src);
                CP_ASYNC16(sb + V0 + buf + kvOff0 + g * 2048, src + DIM);
            }
        }
        CP_COMMIT();
        CP_WAIT1();
        __syncthreads();

        const uint32_t kB = sb + K0 + (uint32_t)(t & 1) * 8192u;
        const uint32_t vB = sb + V0 + (uint32_t)(t & 1) * 8192u;

        // ---- S = Q K^T : warp computes 32x64 (2 m-frags) ----
        float accS[2][8][4];
        #pragma unroll
        for (int i = 0; i < 2; i++)
            #pragma unroll
            for (int j = 0; j < 8; j++)
                #pragma unroll
                for (int q = 0; q < 4; q++) accS[i][j][q] = 0.f;

        #pragma unroll
        for (int ds = 0; ds < 4; ds++) {
            const uint32_t kx = (uint32_t)(ds << 5);
            uint32_t aq[2][4], bk[4][4];
            #pragma unroll
            for (int mf = 0; mf < 2; mf++)
                ldsm4(aq[mf], sb + Q0 + (aOffQ[mf] ^ kx));
            #pragma unroll
            for (int p = 0; p < 4; p++)
                ldsm4(bk[p], kB + (bOffK[p] ^ kx));
            #pragma unroll
            for (int mf = 0; mf < 2; mf++)
                #pragma unroll
                for (int nf = 0; nf < 8; nf++)
                    mma_f16(accS[mf][nf], aq[mf],
                            bk[nf >> 1][(nf & 1) * 2],
                            bk[nf >> 1][(nf & 1) * 2 + 1]);
        }

        // ---- online softmax (base 2), per m-frag; l_i sum DEFERRED ----
        uint32_t ph[2][8][2];
        float sm[2][2];
        float al[2][2];
        #pragma unroll
        for (int mf = 0; mf < 2; mf++) {
            float mx0 = -1e30f, mx1 = -1e30f;
            #pragma unroll
            for (int nf = 0; nf < 8; nf++) {
                mx0 = fmaxf(mx0, fmaxf(accS[mf][nf][0], accS[mf][nf][1]));
                mx1 = fmaxf(mx1, fmaxf(accS[mf][nf][2], accS[mf][nf][3]));
            }
            mx0 = fmaxf(mx0, __shfl_xor_sync(0xffffffffu, mx0, 1));
            mx0 = fmaxf(mx0, __shfl_xor_sync(0xffffffffu, mx0, 2));
            mx1 = fmaxf(mx1, __shfl_xor_sync(0xffffffffu, mx1, 1));
            mx1 = fmaxf(mx1, __shfl_xor_sync(0xffffffffu, mx1, 2));

            const float mn0 = fmaxf(m_i[mf][0], mx0), mn1 = fmaxf(m_i[mf][1], mx1);
            al[mf][0] = fexp2(m_i[mf][0] - mn0);
            al[mf][1] = fexp2(m_i[mf][1] - mn1);
            m_i[mf][0] = mn0;  m_i[mf][1] = mn1;

            float s0 = 0.f, s1 = 0.f;
            #pragma unroll
            for (int nf = 0; nf < 8; nf++) {
                __half2 d01 = __floats2half2_rn(accS[mf][nf][0] - mn0,
                                                accS[mf][nf][1] - mn0);
                __half2 d23 = __floats2half2_rn(accS[mf][nf][2] - mn1,
                                                accS[mf][nf][3] - mn1);
                const uint32_t p01 = h2exp2_u(*(const uint32_t*)&d01);
                const uint32_t p23 = h2exp2_u(*(const uint32_t*)&d23);
                ph[mf][nf][0] = p01;  ph[mf][nf][1] = p23;
                const float2 f01 = __half22float2(*(const __half2*)&p01);
                const float2 f23 = __half22float2(*(const __half2*)&p23);
                s0 += f01.x + f01.y;
                s1 += f23.x + f23.y;
            }
            sm[mf][0] = s0;  sm[mf][1] = s1;
            #pragma unroll
            for (int nf = 0; nf < 8; nf++) {
                accO[mf][nf][0] *= al[mf][0]; accO[mf][nf][1] *= al[mf][0];
                accO[mf][nf][2] *= al[mf][1]; accO[mf][nf][3] *= al[mf][1];
            }
        }

        // ---- O += P V, P from registers (C-frag == A-frag per m-frag) ----
        #pragma unroll
        for (int ks = 0; ks < 4; ks++) {
            uint32_t bv[4][4];
            #pragma unroll
            for (int p = 0; p < 4; p++)
                ldsm4t(bv[p], vB + bOffV[p] + (uint32_t)(ks * 2048));
            #pragma unroll
            for (int mf = 0; mf < 2; mf++) {
                uint32_t ap[4] = { ph[mf][2 * ks][0], ph[mf][2 * ks][1],
                                   ph[mf][2 * ks + 1][0], ph[mf][2 * ks + 1][1] };
                #pragma unroll
                for (int nf = 0; nf < 8; nf++)
                    mma_f16(accO[mf][nf], ap,
                            bv[nf >> 1][(nf & 1) * 2],
                            bv[nf >> 1][(nf & 1) * 2 + 1]);
            }
        }

        // ---- deferred l_i sum reductions (overlap shfl latency with MMAs) ----
        #pragma unroll
        for (int mf = 0; mf < 2; mf++) {
            float s0 = sm[mf][0], s1 = sm[mf][1];
            s0 += __shfl_xor_sync(0xffffffffu, s0, 1);
            s0 += __shfl_xor_sync(0xffffffffu, s0, 2);
            s1 += __shfl_xor_sync(0xffffffffu, s1, 1);
            s1 += __shfl_xor_sync(0xffffffffu, s1, 2);
            l_i[mf][0] = l_i[mf][0] * al[mf][0] + s0;
            l_i[mf][1] = l_i[mf][1] * al[mf][1] + s1;
        }
        __syncthreads();   // compute done before next iter's prefetch overwrites
    }

    // ---- normalize + store (half) ----
    #pragma unroll
    for (int mf = 0; mf < 2; mf++) {
        const int r0 = wid * 32 + mf * 16 + (lane >> 2);
        #pragma unroll
        for (int half = 0; half < 2; half++) {
            const int r = r0 + half * 8;
            const float inv = 1.0f / l_i[mf][half];
            __half* op = out + (size_t)(b * SEQ + q0 + r) * DIM + h * HDIM;
            #pragma unroll
            for (int nf = 0; nf < 8; nf++)
                *(__half2*)(op + nf * 8 + (lane & 3) * 2) =
                    __floats2half2_rn(accO[mf][nf][half * 2] * inv,
                                      accO[mf][nf][half * 2 + 1] * inv);
        }
    }
}

// ---------------------------------------------------------------------------
// Host entry
// ---------------------------------------------------------------------------
extern "C" void kernel_launch(void* const* d_in, const int* in_sizes, int n_in,
                              void* d_out, int out_size)
{
    const float* x     = (const float*)d_in[0];
    const float* ln_g  = (const float*)d_in[1];
    const float* ln_b  = (const float*)d_in[2];
    const float* w_qkv = (const float*)d_in[3];
    const float* b_qkv = (const float*)d_in[4];
    const float* w_out = (const float*)d_in[5];
    const float* b_out = (const float*)d_in[6];
    const float* w_fc1 = (const float*)d_in[7];
    const float* b_fc1 = (const float*)d_in[8];
    const float* w_fc2 = (const float*)d_in[9];
    const float* b_fc2 = (const float*)d_in[10];
    float* out = (float*)d_out;

    __half *p_lnh, *p_qkvh, *p_atth, *p_hh;
    __half *p_wqkv, *p_wout, *p_wfc1, *p_wfc2;
    float  *p_x1;
    cudaGetSymbolAddress((void**)&p_lnh,  g_lnh);
    cudaGetSymbolAddress((void**)&p_qkvh, g_qkvh);
    cudaGetSymbolAddress((void**)&p_atth, g_atth);
    cudaGetSymbolAddress((void**)&p_hh,   g_hh);
    cudaGetSymbolAddress((void**)&p_x1,   g_x1);
    cudaGetSymbolAddress((void**)&p_wqkv, g_wqkvh);
    cudaGetSymbolAddress((void**)&p_wout, g_wouth);
    cudaGetSymbolAddress((void**)&p_wfc1, g_wfc1h);
    cudaGetSymbolAddress((void**)&p_wfc2, g_wfc2h);

    const int SMEM_G = 98304;   // GEMM: 3 stages x 32KB
    const int SMEM_A = 49152;   // attn: Q16 + K16 + V16
    cudaFuncSetAttribute(tgemm_kernel<0, true>,
        cudaFuncAttributeMaxDynamicSharedMemorySize, SMEM_G);
    cudaFuncSetAttribute(tgemm_kernel<1, true>,
        cudaFuncAttributeMaxDynamicSharedMemorySize, SMEM_G);
    cudaFuncSetAttribute(tgemm_kernel<2, false>,
        cudaFuncAttributeMaxDynamicSharedMemorySize, SMEM_G);
    cudaFuncSetAttribute(attn_kernel,
        cudaFuncAttributeMaxDynamicSharedMemorySize, SMEM_A);

    // 0) convert all weights to fp16 (single launch)
    const int n0 = QKVD * DIM, n1 = DIM * DIM, n2 = HID * DIM, n3 = DIM * HID;
    const int nAll = n0 + n1 + n2 + n3;
    f2h_all_kernel<<<(nAll / 4 + 255) / 256, 256>>>(
        w_qkv, p_wqkv, n0, w_out, p_wout, n1,
        w_fc1, p_wfc1, n2, w_fc2, p_wfc2, n3);

    // 1) ln1 = LN(x) -> half
    ln_kernel<<<ROWS, 192>>>(x, ln_g, ln_b, p_lnh);

    // 2) qkv = ln1 @ w_qkv^T + b_qkv -> half
    tgemm_kernel<0, true><<<dim3(QKVD / 128, ROWS / 128), 128, SMEM_G>>>(
        p_lnh, p_wqkv, b_qkv, nullptr, p_qkvh, ROWS, QKVD, DIM);

    // 3) fused attention -> half
    attn_kernel<<<dim3(SEQ / 128, HEADS, BATCH), 128, SMEM_A>>>(p_qkvh, p_atth);

    // 4) x1 = x + att @ w_out^T + b_out  (fp32)
    tgemm_kernel<2, false><<<dim3(DIM / 128, ROWS / 128), 128, SMEM_G>>>(
        p_atth, p_wout, b_out, x, p_x1, ROWS, DIM, DIM);

    // 5) ln2 = LN(x1) -> half
    ln_kernel<<<ROWS, 192>>>(p_x1, ln_g, ln_b, p_lnh);

    // 6) h = gelu(ln2 @ w_fc1^T + b_fc1) -> half
    tgemm_kernel<1, true><<<dim3(HID / 128, ROWS / 128), 128, SMEM_G>>>(
        p_lnh, p_wfc1, b_fc1, nullptr, p_hh, ROWS, HID, DIM);

    // 7) out = x1 + h @ w_fc2^T + b_fc2  (fp32)
    tgemm_kernel<2, false><<<dim3(DIM / 128, ROWS / 128), 128, SMEM_G>>>(
        p_hh, p_wfc2, b_fc2, p_x1, out, ROWS, DIM, HID);
}

// round 15
// speedup vs baseline: 1.0264x; 1.0264x over previous
#include <cuda_runtime.h>
#include <cuda_fp16.h>
#include <cstdint>
#include <math.h>

// ---------------------------------------------------------------------------
// Problem constants
// ---------------------------------------------------------------------------
#define BATCH 16
#define SEQ   1024
#define DIM   768
#define HEADS 12
#define HDIM  64
#define HID   3072
#define ROWS  (BATCH*SEQ)     // 16384
#define QKVD  (3*DIM)         // 2304

// ---------------------------------------------------------------------------
// Scratch (device globals — no allocation allowed)
// ---------------------------------------------------------------------------
__device__ __half g_lnh [(size_t)ROWS * DIM];
__device__ __half g_qkvh[(size_t)ROWS * QKVD];
__device__ __half g_atth[(size_t)ROWS * DIM];
__device__ __half g_hh  [(size_t)ROWS * HID];
__device__ float  g_x1  [(size_t)ROWS * DIM];
__device__ __half g_wqkvh[(size_t)QKVD * DIM];
__device__ __half g_wouth[(size_t)DIM * DIM];
__device__ __half g_wfc1h[(size_t)HID * DIM];
__device__ __half g_wfc2h[(size_t)DIM * HID];

// ---------------------------------------------------------------------------
// Helpers
// ---------------------------------------------------------------------------
__device__ __forceinline__ uint32_t smem_u32(const void* p) {
    uint32_t a;
    asm("{ .reg .u64 t; cvta.to.shared.u64 t, %1; cvt.u32.u64 %0, t; }" : "=r"(a) : "l"(p));
    return a;
}
__device__ __forceinline__ void ldsm4(uint32_t* r, uint32_t addr) {
    asm volatile("ldmatrix.sync.aligned.m8n8.x4.shared.b16 {%0,%1,%2,%3}, [%4];"
        : "=r"(r[0]), "=r"(r[1]), "=r"(r[2]), "=r"(r[3]) : "r"(addr));
}
__device__ __forceinline__ void ldsm4t(uint32_t* r, uint32_t addr) {
    asm volatile("ldmatrix.sync.aligned.m8n8.x4.trans.shared.b16 {%0,%1,%2,%3}, [%4];"
        : "=r"(r[0]), "=r"(r[1]), "=r"(r[2]), "=r"(r[3]) : "r"(addr));
}
__device__ __forceinline__ void mma_f16(float* c, const uint32_t* a,
                                        uint32_t b0, uint32_t b1) {
    asm volatile(
        "mma.sync.aligned.m16n8k16.row.col.f32.f16.f16.f32 "
        "{%0,%1,%2,%3}, {%4,%5,%6,%7}, {%8,%9}, {%0,%1,%2,%3};"
        : "+f"(c[0]), "+f"(c[1]), "+f"(c[2]), "+f"(c[3])
        : "r"(a[0]), "r"(a[1]), "r"(a[2]), "r"(a[3]), "r"(b0), "r"(b1));
}
__device__ __forceinline__ uint32_t sw128(uint32_t off) {
    return off ^ ((off >> 3) & 0x70);
}
__device__ __forceinline__ float fexp2(float x) {
    float y; asm("ex2.approx.f32 %0, %1;" : "=f"(y) : "f"(x)); return y;
}
__device__ __forceinline__ uint32_t h2exp2_u(uint32_t x) {
    uint32_t y; asm("ex2.approx.f16x2 %0, %1;" : "=r"(y) : "r"(x)); return y;
}
#define CP_ASYNC16(dst, src) \
    asm volatile("cp.async.cg.shared.global [%0], [%1], 16;" \
                 :: "r"(dst), "l"(src) : "memory")
#define CP_COMMIT() asm volatile("cp.async.commit_group;" ::: "memory")
#define CP_WAIT1()  asm volatile("cp.async.wait_group 1;"  ::: "memory")

// ---------------------------------------------------------------------------
// fp32 -> fp16 conversion, all four weights in one launch
// ---------------------------------------------------------------------------
__global__ void f2h_all_kernel(const float* __restrict__ s0, __half* __restrict__ d0, int n0,
                               const float* __restrict__ s1, __half* __restrict__ d1, int n1,
                               const float* __restrict__ s2, __half* __restrict__ d2, int n2,
                               const float* __restrict__ s3, __half* __restrict__ d3, int n3)
{
    int i = (blockIdx.x * 256 + threadIdx.x) * 4;
    const float* s; __half* d;
    if (i < n0)                   { s = s0; d = d0; }
    else if ((i -= n0) < n1)      { s = s1; d = d1; }
    else if ((i -= n1) < n2)      { s = s2; d = d2; }
    else if ((i -= n2) < n3)      { s = s3; d = d3; }
    else return;
    float4 v = *(const float4*)(s + i);
    *(__half2*)(d + i)     = __floats2half2_rn(v.x, v.y);
    *(__half2*)(d + i + 2) = __floats2half2_rn(v.z, v.w);
}

// ---------------------------------------------------------------------------
// LayerNorm: one block per row (D=768), 192 threads x float4, half out
// ---------------------------------------------------------------------------
__global__ void __launch_bounds__(192)
ln_kernel(const float* __restrict__ x,
          const float* __restrict__ gg,
          const float* __restrict__ bb,
          __half* __restrict__ y)
{
    const int row = blockIdx.x;
    const int tid = threadIdx.x;

    const float4 v = *(const float4*)(x + (size_t)row * DIM + tid * 4);
    float s = v.x + v.y + v.z + v.w;
    float q = v.x*v.x + v.y*v.y + v.z*v.z + v.w*v.w;

    #pragma unroll
    for (int m = 16; m; m >>= 1) {
        s += __shfl_xor_sync(0xffffffffu, s, m);
        q += __shfl_xor_sync(0xffffffffu, q, m);
    }
    __shared__ float sh[12];
    const int warp = tid >> 5, lane = tid & 31;
    if (!lane) { sh[warp] = s; sh[warp + 6] = q; }
    __syncthreads();
    if (tid == 0) {
        float ts = 0.f, tq = 0.f;
        #pragma unroll
        for (int w = 0; w < 6; w++) { ts += sh[w]; tq += sh[w + 6]; }
        sh[0] = ts * (1.0f / DIM);
        sh[6] = tq * (1.0f / DIM);
    }
    __syncthreads();
    const float mean = sh[0];
    const float rstd = rsqrtf(sh[6] - mean * mean + 1e-5f);

    const float4 g4 = *(const float4*)(gg + tid * 4);
    const float4 b4 = *(const float4*)(bb + tid * 4);
    __half2 h0 = __floats2half2_rn((v.x - mean) * rstd * g4.x + b4.x,
                                   (v.y - mean) * rstd * g4.y + b4.y);
    __half2 h1 = __floats2half2_rn((v.z - mean) * rstd * g4.z + b4.z,
                                   (v.w - mean) * rstd * g4.w + b4.w);
    *(__half2*)(y + (size_t)row * DIM + tid * 4)     = h0;
    *(__half2*)(y + (size_t)row * DIM + tid * 4 + 2) = h1;
}

// ---------------------------------------------------------------------------
// fp16 mma.sync GEMM, cp.async 3-stage pipeline + ks-level fragment
// double-buffering (ldsm for ks+1 issued before MMAs of ks).
// CTA tile 128x128, BK=64. 4 warps (2M x 2N), warp tile 64x64 (acc 128 regs).
// 128 threads, __launch_bounds__(128,2): 2 CTAs/SM.
// SMEM: 3 stages x (A 16K + B 16K) = 96KB.
// EPI: 0 = bias, 1 = bias+GELU(exact), 2 = bias+residual(fp32)
// ---------------------------------------------------------------------------
template<int EPI, bool HALF_OUT>
__global__ void __launch_bounds__(128, 2)
tgemm_kernel(const __half* __restrict__ A,
             const __half* __restrict__ W,
             const float* __restrict__ bias,
             const float* __restrict__ res,
             void* __restrict__ Cv,
             int M, int N, int K)
{
    extern __shared__ char smem[];
    const uint32_t sb = smem_u32(smem);
    const int tid   = threadIdx.x;
    const int wid   = tid >> 5;
    const int lane  = tid & 31;
    const int warpM = wid & 1;
    const int warpN = wid >> 1;
    const int m0 = blockIdx.y * 128;
    const int n0 = blockIdx.x * 128;

    uint32_t aOff[4], bOff[4];
    {
        const int r8 = (lane & 7) + ((lane >> 3) & 1) * 8;
        #pragma unroll
        for (int mf = 0; mf < 4; mf++) {
            const int row = warpM * 64 + mf * 16 + r8;
            aOff[mf] = sw128((uint32_t)(row * 128 + (lane >> 4) * 16));
        }
        const int rB = (lane & 7) + ((lane >> 4) & 1) * 8;
        #pragma unroll
        for (int p = 0; p < 4; p++) {
            const int row = warpN * 64 + p * 16 + rB;
            bOff[p] = sw128((uint32_t)(row * 128 + ((lane >> 3) & 1) * 16));
        }
    }

    float acc[4][8][4];
    #pragma unroll
    for (int i = 0; i < 4; i++)
        #pragma unroll
        for (int j = 0; j < 8; j++)
            #pragma unroll
            for (int q = 0; q < 4; q++) acc[i][j][q] = 0.f;

    const int nIter = K >> 6;                 // BK = 64 halfs
    const int lr0  = tid >> 3;
    const int lch  = tid & 7;
    const uint32_t stOff = sw128((uint32_t)(lr0 * 128 + lch * 16));
    const __half* apt = A + (size_t)(m0 + lr0) * K + lch * 8;
    const __half* bpt = W + (size_t)(n0 + lr0) * K + lch * 8;

    #pragma unroll
    for (int s = 0; s < 2; s++) {
        const int k0 = s << 6;
        const uint32_t dstA = sb + (uint32_t)s * 32768u + stOff;
        #pragma unroll
        for (int g = 0; g < 8; g++)
            CP_ASYNC16(dstA + g * 2048, apt + (size_t)g * 16 * K + k0);
        #pragma unroll
        for (int g = 0; g < 8; g++)
            CP_ASYNC16(dstA + 16384 + g * 2048, bpt + (size_t)g * 16 * K + k0);
        CP_COMMIT();
    }

    int slotNext = 2;
    for (int it = 0; it < nIter; ++it) {
        CP_WAIT1();
        __syncthreads();

        if (it + 2 < nIter) {
            const int k0 = (it + 2) << 6;
            const uint32_t dstA = sb + (uint32_t)slotNext * 32768u + stOff;
            #pragma unroll
            for (int g = 0; g < 8; g++)
                CP_ASYNC16(dstA + g * 2048, apt + (size_t)g * 16 * K + k0);
            #pragma unroll
            for (int g = 0; g < 8; g++)
                CP_ASYNC16(dstA + 16384 + g * 2048, bpt + (size_t)g * 16 * K + k0);
        }
        CP_COMMIT();
        slotNext = (slotNext == 2) ? 0 : slotNext + 1;

        const uint32_t aB = sb + (uint32_t)(it % 3) * 32768u;
        const uint32_t bB = aB + 16384u;

        // ks-level double-buffered fragments
        uint32_t af[2][4][4], bf[2][4][4];
        #pragma unroll
        for (int mf = 0; mf < 4; mf++) ldsm4(af[0][mf], aB + aOff[mf]);
        #pragma unroll
        for (int p = 0; p < 4; p++)   ldsm4(bf[0][p],  bB + bOff[p]);

        #pragma unroll
        for (int ks = 0; ks < 4; ks++) {
            const int cur = ks & 1, nxt = cur ^ 1;
            if (ks < 3) {
                const uint32_t kx = (uint32_t)((ks + 1) << 5);
                #pragma unroll
                for (int mf = 0; mf < 4; mf++)
                    ldsm4(af[nxt][mf], aB + (aOff[mf] ^ kx));
                #pragma unroll
                for (int p = 0; p < 4; p++)
                    ldsm4(bf[nxt][p],  bB + (bOff[p]  ^ kx));
            }
            #pragma unroll
            for (int mf = 0; mf < 4; mf++)
                #pragma unroll
                for (int nf = 0; nf < 8; nf++)
                    mma_f16(acc[mf][nf], af[cur][mf],
                            bf[cur][nf >> 1][(nf & 1) * 2],
                            bf[cur][nf >> 1][(nf & 1) * 2 + 1]);
        }
    }

    #pragma unroll
    for (int mf = 0; mf < 4; mf++) {
        const int r0 = m0 + warpM * 64 + mf * 16 + (lane >> 2);
        #pragma unroll
        for (int nf = 0; nf < 8; nf++) {
            const int col = n0 + warpN * 64 + nf * 8 + (lane & 3) * 2;
            const float b0 = bias[col], b1 = bias[col + 1];
            #pragma unroll
            for (int h = 0; h < 2; h++) {
                const int r = r0 + h * 8;
                float v0 = acc[mf][nf][h * 2 + 0] + b0;
                float v1 = acc[mf][nf][h * 2 + 1] + b1;
                if (EPI == 1) {
                    v0 = 0.5f * v0 * (1.0f + erff(v0 * 0.70710678118654752f));
                    v1 = 0.5f * v1 * (1.0f + erff(v1 * 0.70710678118654752f));
                }
                if (EPI == 2) {
                    const float2 rr = *(const float2*)(res + (size_t)r * N + col);
                    v0 += rr.x; v1 += rr.y;
                }
                if (HALF_OUT) {
                    *(__half2*)((__half*)Cv + (size_t)r * N + col) =
                        __floats2half2_rn(v0, v1);
                } else {
                    *(float2*)((float*)Cv + (size_t)r * N + col) =
                        make_float2(v0, v1);
                }
            }
        }
    }
}

// ---------------------------------------------------------------------------
// fp16 tensor-core flash attention (R13 proven config, reverted/frozen).
// 128 threads, 4 warps x 32 q-rows; register-resident P; base-2 softmax.
// SMEM: Q 16K @0 | K 2x8K @16384 | V 2x8K @32768 = 48KB. 2 CTAs/SM.
// ---------------------------------------------------------------------------
__global__ void __launch_bounds__(128, 2)
attn_kernel(const __half* __restrict__ qkv, __half* __restrict__ out)
{
    extern __shared__ char smem[];
    const uint32_t sb = smem_u32(smem);
    const uint32_t Q0 = 0u, K0 = 16384u, V0 = 32768u;

    const int b  = blockIdx.z;
    const int h  = blockIdx.y;
    const int q0 = blockIdx.x * 128;
    const int tid = threadIdx.x, wid = tid >> 5, lane = tid & 31;

    const float qs = 0.03608439182435162f * 1.4426950408889634f;

    const int krow = tid >> 3;          // 0..15 (+g*16)
    const int kch  = tid & 7;
    const uint32_t kvOff0 = sw128((uint32_t)(krow * 128 + kch * 16));

    // ---- load Q tile 128x64, pre-scaled in fp32 ----
    #pragma unroll
    for (int g = 0; g < 8; g++) {
        const int idx = tid + g * 128;
        const int row = idx >> 3, ch = idx & 7;
        const __half* qp = qkv + (size_t)(b * SEQ + q0 + row) * QKVD + h * HDIM + ch * 8;
        uint4 raw = *(const uint4*)qp;
        __half2* hp = (__half2*)&raw;
        #pragma unroll
        for (int j = 0; j < 4; j++) {
            float2 f = __half22float2(hp[j]);
            hp[j] = __floats2half2_rn(f.x * qs, f.y * qs);
        }
        *(uint4*)(smem + Q0 + sw128((uint32_t)(row * 128 + ch * 16))) = raw;
    }

    // ---- prefetch KV tile 0 ----
    {
        const __half* kp = qkv + (size_t)(b * SEQ + krow) * QKVD + DIM + h * HDIM + kch * 8;
        #pragma unroll
        for (int g = 0; g < 4; g++) {
            const __half* src = kp + (size_t)g * 16 * QKVD;
            CP_ASYNC16(sb + K0 + kvOff0 + g * 2048, src);
            CP_ASYNC16(sb + V0 + kvOff0 + g * 2048, src + DIM);
        }
        CP_COMMIT();
    }

    // ---- fragment offsets (warp owns q-rows [wid*32, wid*32+32)) ----
    uint32_t aOffQ[2], bOffK[4], bOffV[4];
    {
        const int r8 = (lane & 7) + ((lane >> 3) & 1) * 8;
        #pragma unroll
        for (int mf = 0; mf < 2; mf++)
            aOffQ[mf] = sw128((uint32_t)((wid * 32 + mf * 16 + r8) * 128
                                         + (lane >> 4) * 16));
        const int rB = (lane & 7) + ((lane >> 4) & 1) * 8;
        #pragma unroll
        for (int p = 0; p < 4; p++)
            bOffK[p] = sw128((uint32_t)((p * 16 + rB) * 128 + ((lane >> 3) & 1) * 16));
        #pragma unroll
        for (int p = 0; p < 4; p++)
            bOffV[p] = sw128((uint32_t)(r8 * 128 + p * 32 + ((lane >> 4) & 1) * 16));
    }

    float accO[2][8][4];
    #pragma unroll
    for (int i = 0; i < 2; i++)
        #pragma unroll
        for (int j = 0; j < 8; j++)
            #pragma unroll
            for (int q = 0; q < 4; q++) accO[i][j][q] = 0.f;
    float m_i[2][2] = {{-1e30f, -1e30f}, {-1e30f, -1e30f}};
    float l_i[2][2] = {{0.f, 0.f}, {0.f, 0.f}};

    for (int t = 0; t < SEQ / 64; t++) {
        if (t + 1 < SEQ / 64) {
            const uint32_t buf = (uint32_t)((t + 1) & 1) * 8192u;
            const __half* kp = qkv + (size_t)(b * SEQ + (t + 1) * 64 + krow) * QKVD
                               + DIM + h * HDIM + kch * 8;
            #pragma unroll
            for (int g = 0; g < 4; g++) {
                const __half* src = kp + (size_t)g * 16 * QKVD;
                CP_ASYNC16(sb + K0 + buf + kvOff0 + g * 2048, src);
                CP_ASYNC16(sb + V0 + buf + kvOff0 + g * 2048, src + DIM);
            }
        }
        CP_COMMIT();
        CP_WAIT1();
        __syncthreads();

        const uint32_t kB = sb + K0 + (uint32_t)(t & 1) * 8192u;
        const uint32_t vB = sb + V0 + (uint32_t)(t & 1) * 8192u;

        // ---- S = Q K^T : warp computes 32x64 (2 m-frags) ----
        float accS[2][8][4];
        #pragma unroll
        for (int i = 0; i < 2; i++)
            #pragma unroll
            for (int j = 0; j < 8; j++)
                #pragma unroll
                for (int q = 0; q < 4; q++) accS[i][j][q] = 0.f;

        #pragma unroll
        for (int ds = 0; ds < 4; ds++) {
            const uint32_t kx = (uint32_t)(ds << 5);
            uint32_t aq[2][4], bk[4][4];
            #pragma unroll
            for (int mf = 0; mf < 2; mf++)
                ldsm4(aq[mf], sb + Q0 + (aOffQ[mf] ^ kx));
            #pragma unroll
            for (int p = 0; p < 4; p++)
                ldsm4(bk[p], kB + (bOffK[p] ^ kx));
            #pragma unroll
            for (int mf = 0; mf < 2; mf++)
                #pragma unroll
                for (int nf = 0; nf < 8; nf++)
                    mma_f16(accS[mf][nf], aq[mf],
                            bk[nf >> 1][(nf & 1) * 2],
                            bk[nf >> 1][(nf & 1) * 2 + 1]);
        }

        // ---- online softmax (base 2), per m-frag ----
        uint32_t ph[2][8][2];
        #pragma unroll
        for (int mf = 0; mf < 2; mf++) {
            float mx0 = -1e30f, mx1 = -1e30f;
            #pragma unroll
            for (int nf = 0; nf < 8; nf++) {
                mx0 = fmaxf(mx0, fmaxf(accS[mf][nf][0], accS[mf][nf][1]));
                mx1 = fmaxf(mx1, fmaxf(accS[mf][nf][2], accS[mf][nf][3]));
            }
            mx0 = fmaxf(mx0, __shfl_xor_sync(0xffffffffu, mx0, 1));
            mx0 = fmaxf(mx0, __shfl_xor_sync(0xffffffffu, mx0, 2));
            mx1 = fmaxf(mx1, __shfl_xor_sync(0xffffffffu, mx1, 1));
            mx1 = fmaxf(mx1, __shfl_xor_sync(0xffffffffu, mx1, 2));

            const float mn0 = fmaxf(m_i[mf][0], mx0), mn1 = fmaxf(m_i[mf][1], mx1);
            const float al0 = fexp2(m_i[mf][0] - mn0), al1 = fexp2(m_i[mf][1] - mn1);

            float s0 = 0.f, s1 = 0.f;
            #pragma unroll
            for (int nf = 0; nf < 8; nf++) {
                __half2 d01 = __floats2half2_rn(accS[mf][nf][0] - mn0,
                                                accS[mf][nf][1] - mn0);
                __half2 d23 = __floats2half2_rn(accS[mf][nf][2] - mn1,
                                                accS[mf][nf][3] - mn1);
                const uint32_t p01 = h2exp2_u(*(const uint32_t*)&d01);
                const uint32_t p23 = h2exp2_u(*(const uint32_t*)&d23);
                ph[mf][nf][0] = p01;  ph[mf][nf][1] = p23;
                const float2 f01 = __half22float2(*(const __half2*)&p01);
                const float2 f23 = __half22float2(*(const __half2*)&p23);
                s0 += f01.x + f01.y;
                s1 += f23.x + f23.y;
            }
            s0 += __shfl_xor_sync(0xffffffffu, s0, 1);
            s0 += __shfl_xor_sync(0xffffffffu, s0, 2);
            s1 += __shfl_xor_sync(0xffffffffu, s1, 1);
            s1 += __shfl_xor_sync(0xffffffffu, s1, 2);
            l_i[mf][0] = l_i[mf][0] * al0 + s0;  m_i[mf][0] = mn0;
            l_i[mf][1] = l_i[mf][1] * al1 + s1;  m_i[mf][1] = mn1;
            #pragma unroll
            for (int nf = 0; nf < 8; nf++) {
                accO[mf][nf][0] *= al0; accO[mf][nf][1] *= al0;
                accO[mf][nf][2] *= al1; accO[mf][nf][3] *= al1;
            }
        }

        // ---- O += P V, P from registers (C-frag == A-frag per m-frag) ----
        #pragma unroll
        for (int ks = 0; ks < 4; ks++) {
            uint32_t bv[4][4];
            #pragma unroll
            for (int p = 0; p < 4; p++)
                ldsm4t(bv[p], vB + bOffV[p] + (uint32_t)(ks * 2048));
            #pragma unroll
            for (int mf = 0; mf < 2; mf++) {
                uint32_t ap[4] = { ph[mf][2 * ks][0], ph[mf][2 * ks][1],
                                   ph[mf][2 * ks + 1][0], ph[mf][2 * ks + 1][1] };
                #pragma unroll
                for (int nf = 0; nf < 8; nf++)
                    mma_f16(accO[mf][nf], ap,
                            bv[nf >> 1][(nf & 1) * 2],
                            bv[nf >> 1][(nf & 1) * 2 + 1]);
            }
        }
        __syncthreads();   // compute done before next iter's prefetch overwrites
    }

    // ---- normalize + store (half) ----
    #pragma unroll
    for (int mf = 0; mf < 2; mf++) {
        const int r0 = wid * 32 + mf * 16 + (lane >> 2);
        #pragma unroll
        for (int half = 0; half < 2; half++) {
            const int r = r0 + half * 8;
            const float inv = 1.0f / l_i[mf][half];
            __half* op = out + (size_t)(b * SEQ + q0 + r) * DIM + h * HDIM;
            #pragma unroll
            for (int nf = 0; nf < 8; nf++)
                *(__half2*)(op + nf * 8 + (lane & 3) * 2) =
                    __floats2half2_rn(accO[mf][nf][half * 2] * inv,
                                      accO[mf][nf][half * 2 + 1] * inv);
        }
    }
}

// ---------------------------------------------------------------------------
// Host entry
// ---------------------------------------------------------------------------
extern "C" void kernel_launch(void* const* d_in, const int* in_sizes, int n_in,
                              void* d_out, int out_size)
{
    const float* x     = (const float*)d_in[0];
    const float* ln_g  = (const float*)d_in[1];
    const float* ln_b  = (const float*)d_in[2];
    const float* w_qkv = (const float*)d_in[3];
    const float* b_qkv = (const float*)d_in[4];
    const float* w_out = (const float*)d_in[5];
    const float* b_out = (const float*)d_in[6];
    const float* w_fc1 = (const float*)d_in[7];
    const float* b_fc1 = (const float*)d_in[8];
    const float* w_fc2 = (const float*)d_in[9];
    const float* b_fc2 = (const float*)d_in[10];
    float* out = (float*)d_out;

    __half *p_lnh, *p_qkvh, *p_atth, *p_hh;
    __half *p_wqkv, *p_wout, *p_wfc1, *p_wfc2;
    float  *p_x1;
    cudaGetSymbolAddress((void**)&p_lnh,  g_lnh);
    cudaGetSymbolAddress((void**)&p_qkvh, g_qkvh);
    cudaGetSymbolAddress((void**)&p_atth, g_atth);
    cudaGetSymbolAddress((void**)&p_hh,   g_hh);
    cudaGetSymbolAddress((void**)&p_x1,   g_x1);
    cudaGetSymbolAddress((void**)&p_wqkv, g_wqkvh);
    cudaGetSymbolAddress((void**)&p_wout, g_wouth);
    cudaGetSymbolAddress((void**)&p_wfc1, g_wfc1h);
    cudaGetSymbolAddress((void**)&p_wfc2, g_wfc2h);

    const int SMEM_G = 98304;   // GEMM: 3 stages x 32KB
    const int SMEM_A = 49152;   // attn: Q16 + K16 + V16
    cudaFuncSetAttribute(tgemm_kernel<0, true>,
        cudaFuncAttributeMaxDynamicSharedMemorySize, SMEM_G);
    cudaFuncSetAttribute(tgemm_kernel<1, true>,
        cudaFuncAttributeMaxDynamicSharedMemorySize, SMEM_G);
    cudaFuncSetAttribute(tgemm_kernel<2, false>,
        cudaFuncAttributeMaxDynamicSharedMemorySize, SMEM_G);
    cudaFuncSetAttribute(attn_kernel,
        cudaFuncAttributeMaxDynamicSharedMemorySize, SMEM_A);

    // 0) convert all weights to fp16 (single launch)
    const int n0 = QKVD * DIM, n1 = DIM * DIM, n2 = HID * DIM, n3 = DIM * HID;
    const int nAll = n0 + n1 + n2 + n3;
    f2h_all_kernel<<<(nAll / 4 + 255) / 256, 256>>>(
        w_qkv, p_wqkv, n0, w_out, p_wout, n1,
        w_fc1, p_wfc1, n2, w_fc2, p_wfc2, n3);

    // 1) ln1 = LN(x) -> half
    ln_kernel<<<ROWS, 192>>>(x, ln_g, ln_b, p_lnh);

    // 2) qkv = ln1 @ w_qkv^T + b_qkv -> half
    tgemm_kernel<0, true><<<dim3(QKVD / 128, ROWS / 128), 128, SMEM_G>>>(
        p_lnh, p_wqkv, b_qkv, nullptr, p_qkvh, ROWS, QKVD, DIM);

    // 3) fused attention -> half
    attn_kernel<<<dim3(SEQ / 128, HEADS, BATCH), 128, SMEM_A>>>(p_qkvh, p_atth);

    // 4) x1 = x + att @ w_out^T + b_out  (fp32)
    tgemm_kernel<2, false><<<dim3(DIM / 128, ROWS / 128), 128, SMEM_G>>>(
        p_atth, p_wout, b_out, x, p_x1, ROWS, DIM, DIM);

    // 5) ln2 = LN(x1) -> half
    ln_kernel<<<ROWS, 192>>>(p_x1, ln_g, ln_b, p_lnh);

    // 6) h = gelu(ln2 @ w_fc1^T + b_fc1) -> half
    tgemm_kernel<1, true><<<dim3(HID / 128, ROWS / 128), 128, SMEM_G>>>(
        p_lnh, p_wfc1, b_fc1, nullptr, p_hh, ROWS, HID, DIM);

    // 7) out = x1 + h @ w_fc2^T + b_fc2  (fp32)
    tgemm_kernel<2, false><<<dim3(DIM / 128, ROWS / 128), 128, SMEM_G>>>(
        p_hh, p_wfc2, b_fc2, p_x1, out, ROWS, DIM, HID);
}

// round 16
// speedup vs baseline: 1.0562x; 1.0291x over previous
#include <cuda_runtime.h>
#include <cuda_fp16.h>
#include <cstdint>
#include <math.h>

// ---------------------------------------------------------------------------
// Problem constants
// ---------------------------------------------------------------------------
#define BATCH 16
#define SEQ   1024
#define DIM   768
#define HEADS 12
#define HDIM  64
#define HID   3072
#define ROWS  (BATCH*SEQ)     // 16384
#define QKVD  (3*DIM)         // 2304

// ---------------------------------------------------------------------------
// Scratch (device globals — no allocation allowed)
// ---------------------------------------------------------------------------
__device__ __half g_lnh [(size_t)ROWS * DIM];
__device__ __half g_qkvh[(size_t)ROWS * QKVD];
__device__ __half g_atth[(size_t)ROWS * DIM];
__device__ __half g_hh  [(size_t)ROWS * HID];
__device__ float  g_x1  [(size_t)ROWS * DIM];
__device__ __half g_wqkvh[(size_t)QKVD * DIM];
__device__ __half g_wouth[(size_t)DIM * DIM];
__device__ __half g_wfc1h[(size_t)HID * DIM];
__device__ __half g_wfc2h[(size_t)DIM * HID];

// ---------------------------------------------------------------------------
// Helpers
// ---------------------------------------------------------------------------
__device__ __forceinline__ uint32_t smem_u32(const void* p) {
    uint32_t a;
    asm("{ .reg .u64 t; cvta.to.shared.u64 t, %1; cvt.u32.u64 %0, t; }" : "=r"(a) : "l"(p));
    return a;
}
__device__ __forceinline__ void ldsm4(uint32_t* r, uint32_t addr) {
    asm volatile("ldmatrix.sync.aligned.m8n8.x4.shared.b16 {%0,%1,%2,%3}, [%4];"
        : "=r"(r[0]), "=r"(r[1]), "=r"(r[2]), "=r"(r[3]) : "r"(addr));
}
__device__ __forceinline__ void ldsm4t(uint32_t* r, uint32_t addr) {
    asm volatile("ldmatrix.sync.aligned.m8n8.x4.trans.shared.b16 {%0,%1,%2,%3}, [%4];"
        : "=r"(r[0]), "=r"(r[1]), "=r"(r[2]), "=r"(r[3]) : "r"(addr));
}
__device__ __forceinline__ void mma_f16(float* c, const uint32_t* a,
                                        uint32_t b0, uint32_t b1) {
    asm volatile(
        "mma.sync.aligned.m16n8k16.row.col.f32.f16.f16.f32 "
        "{%0,%1,%2,%3}, {%4,%5,%6,%7}, {%8,%9}, {%0,%1,%2,%3};"
        : "+f"(c[0]), "+f"(c[1]), "+f"(c[2]), "+f"(c[3])
        : "r"(a[0]), "r"(a[1]), "r"(a[2]), "r"(a[3]), "r"(b0), "r"(b1));
}
// fp16-accumulate variant: C/D = 2 regs (half2 x2: row r, row r+8)
__device__ __forceinline__ void mma_h16(uint32_t* c, const uint32_t* a,
                                        uint32_t b0, uint32_t b1) {
    asm volatile(
        "mma.sync.aligned.m16n8k16.row.col.f16.f16.f16.f16 "
        "{%0,%1}, {%2,%3,%4,%5}, {%6,%7}, {%0,%1};"
        : "+r"(c[0]), "+r"(c[1])
        : "r"(a[0]), "r"(a[1]), "r"(a[2]), "r"(a[3]), "r"(b0), "r"(b1));
}
__device__ __forceinline__ uint32_t sw128(uint32_t off) {
    return off ^ ((off >> 3) & 0x70);
}
__device__ __forceinline__ float fexp2(float x) {
    float y; asm("ex2.approx.f32 %0, %1;" : "=f"(y) : "f"(x)); return y;
}
__device__ __forceinline__ uint32_t h2exp2_u(uint32_t x) {
    uint32_t y; asm("ex2.approx.f16x2 %0, %1;" : "=r"(y) : "r"(x)); return y;
}
#define CP_ASYNC16(dst, src) \
    asm volatile("cp.async.cg.shared.global [%0], [%1], 16;" \
                 :: "r"(dst), "l"(src) : "memory")
#define CP_COMMIT() asm volatile("cp.async.commit_group;" ::: "memory")
#define CP_WAIT1()  asm volatile("cp.async.wait_group 1;"  ::: "memory")

// ---------------------------------------------------------------------------
// fp32 -> fp16 conversion, all four weights in one launch
// ---------------------------------------------------------------------------
__global__ void f2h_all_kernel(const float* __restrict__ s0, __half* __restrict__ d0, int n0,
                               const float* __restrict__ s1, __half* __restrict__ d1, int n1,
                               const float* __restrict__ s2, __half* __restrict__ d2, int n2,
                               const float* __restrict__ s3, __half* __restrict__ d3, int n3)
{
    int i = (blockIdx.x * 256 + threadIdx.x) * 4;
    const float* s; __half* d;
    if (i < n0)                   { s = s0; d = d0; }
    else if ((i -= n0) < n1)      { s = s1; d = d1; }
    else if ((i -= n1) < n2)      { s = s2; d = d2; }
    else if ((i -= n2) < n3)      { s = s3; d = d3; }
    else return;
    float4 v = *(const float4*)(s + i);
    *(__half2*)(d + i)     = __floats2half2_rn(v.x, v.y);
    *(__half2*)(d + i + 2) = __floats2half2_rn(v.z, v.w);
}

// ---------------------------------------------------------------------------
// LayerNorm: one block per row (D=768), 192 threads x float4, half out
// ---------------------------------------------------------------------------
__global__ void __launch_bounds__(192)
ln_kernel(const float* __restrict__ x,
          const float* __restrict__ gg,
          const float* __restrict__ bb,
          __half* __restrict__ y)
{
    const int row = blockIdx.x;
    const int tid = threadIdx.x;

    const float4 v = *(const float4*)(x + (size_t)row * DIM + tid * 4);
    float s = v.x + v.y + v.z + v.w;
    float q = v.x*v.x + v.y*v.y + v.z*v.z + v.w*v.w;

    #pragma unroll
    for (int m = 16; m; m >>= 1) {
        s += __shfl_xor_sync(0xffffffffu, s, m);
        q += __shfl_xor_sync(0xffffffffu, q, m);
    }
    __shared__ float sh[12];
    const int warp = tid >> 5, lane = tid & 31;
    if (!lane) { sh[warp] = s; sh[warp + 6] = q; }
    __syncthreads();
    if (tid == 0) {
        float ts = 0.f, tq = 0.f;
        #pragma unroll
        for (int w = 0; w < 6; w++) { ts += sh[w]; tq += sh[w + 6]; }
        sh[0] = ts * (1.0f / DIM);
        sh[6] = tq * (1.0f / DIM);
    }
    __syncthreads();
    const float mean = sh[0];
    const float rstd = rsqrtf(sh[6] - mean * mean + 1e-5f);

    const float4 g4 = *(const float4*)(gg + tid * 4);
    const float4 b4 = *(const float4*)(bb + tid * 4);
    __half2 h0 = __floats2half2_rn((v.x - mean) * rstd * g4.x + b4.x,
                                   (v.y - mean) * rstd * g4.y + b4.y);
    __half2 h1 = __floats2half2_rn((v.z - mean) * rstd * g4.z + b4.z,
                                   (v.w - mean) * rstd * g4.w + b4.w);
    *(__half2*)(y + (size_t)row * DIM + tid * 4)     = h0;
    *(__half2*)(y + (size_t)row * DIM + tid * 4 + 2) = h1;
}

// ---------------------------------------------------------------------------
// fp16 mma.sync GEMM (R15 config, frozen).
// CTA tile 128x128, BK=64. 4 warps (2M x 2N), warp tile 64x64.
// 128 threads, __launch_bounds__(128,2); SMEM 3 x 32KB; f32 accumulate.
// EPI: 0 = bias, 1 = bias+GELU(exact), 2 = bias+residual(fp32)
// ---------------------------------------------------------------------------
template<int EPI, bool HALF_OUT>
__global__ void __launch_bounds__(128, 2)
tgemm_kernel(const __half* __restrict__ A,
             const __half* __restrict__ W,
             const float* __restrict__ bias,
             const float* __restrict__ res,
             void* __restrict__ Cv,
             int M, int N, int K)
{
    extern __shared__ char smem[];
    const uint32_t sb = smem_u32(smem);
    const int tid   = threadIdx.x;
    const int wid   = tid >> 5;
    const int lane  = tid & 31;
    const int warpM = wid & 1;
    const int warpN = wid >> 1;
    const int m0 = blockIdx.y * 128;
    const int n0 = blockIdx.x * 128;

    uint32_t aOff[4], bOff[4];
    {
        const int r8 = (lane & 7) + ((lane >> 3) & 1) * 8;
        #pragma unroll
        for (int mf = 0; mf < 4; mf++) {
            const int row = warpM * 64 + mf * 16 + r8;
            aOff[mf] = sw128((uint32_t)(row * 128 + (lane >> 4) * 16));
        }
        const int rB = (lane & 7) + ((lane >> 4) & 1) * 8;
        #pragma unroll
        for (int p = 0; p < 4; p++) {
            const int row = warpN * 64 + p * 16 + rB;
            bOff[p] = sw128((uint32_t)(row * 128 + ((lane >> 3) & 1) * 16));
        }
    }

    float acc[4][8][4];
    #pragma unroll
    for (int i = 0; i < 4; i++)
        #pragma unroll
        for (int j = 0; j < 8; j++)
            #pragma unroll
            for (int q = 0; q < 4; q++) acc[i][j][q] = 0.f;

    const int nIter = K >> 6;                 // BK = 64 halfs
    const int lr0  = tid >> 3;
    const int lch  = tid & 7;
    const uint32_t stOff = sw128((uint32_t)(lr0 * 128 + lch * 16));
    const __half* apt = A + (size_t)(m0 + lr0) * K + lch * 8;
    const __half* bpt = W + (size_t)(n0 + lr0) * K + lch * 8;

    #pragma unroll
    for (int s = 0; s < 2; s++) {
        const int k0 = s << 6;
        const uint32_t dstA = sb + (uint32_t)s * 32768u + stOff;
        #pragma unroll
        for (int g = 0; g < 8; g++)
            CP_ASYNC16(dstA + g * 2048, apt + (size_t)g * 16 * K + k0);
        #pragma unroll
        for (int g = 0; g < 8; g++)
            CP_ASYNC16(dstA + 16384 + g * 2048, bpt + (size_t)g * 16 * K + k0);
        CP_COMMIT();
    }

    int slotNext = 2;
    for (int it = 0; it < nIter; ++it) {
        CP_WAIT1();
        __syncthreads();

        if (it + 2 < nIter) {
            const int k0 = (it + 2) << 6;
            const uint32_t dstA = sb + (uint32_t)slotNext * 32768u + stOff;
            #pragma unroll
            for (int g = 0; g < 8; g++)
                CP_ASYNC16(dstA + g * 2048, apt + (size_t)g * 16 * K + k0);
            #pragma unroll
            for (int g = 0; g < 8; g++)
                CP_ASYNC16(dstA + 16384 + g * 2048, bpt + (size_t)g * 16 * K + k0);
        }
        CP_COMMIT();
        slotNext = (slotNext == 2) ? 0 : slotNext + 1;

        const uint32_t aB = sb + (uint32_t)(it % 3) * 32768u;
        const uint32_t bB = aB + 16384u;

        // ks-level double-buffered fragments
        uint32_t af[2][4][4], bf[2][4][4];
        #pragma unroll
        for (int mf = 0; mf < 4; mf++) ldsm4(af[0][mf], aB + aOff[mf]);
        #pragma unroll
        for (int p = 0; p < 4; p++)   ldsm4(bf[0][p],  bB + bOff[p]);

        #pragma unroll
        for (int ks = 0; ks < 4; ks++) {
            const int cur = ks & 1, nxt = cur ^ 1;
            if (ks < 3) {
                const uint32_t kx = (uint32_t)((ks + 1) << 5);
                #pragma unroll
                for (int mf = 0; mf < 4; mf++)
                    ldsm4(af[nxt][mf], aB + (aOff[mf] ^ kx));
                #pragma unroll
                for (int p = 0; p < 4; p++)
                    ldsm4(bf[nxt][p],  bB + (bOff[p]  ^ kx));
            }
            #pragma unroll
            for (int mf = 0; mf < 4; mf++)
                #pragma unroll
                for (int nf = 0; nf < 8; nf++)
                    mma_f16(acc[mf][nf], af[cur][mf],
                            bf[cur][nf >> 1][(nf & 1) * 2],
                            bf[cur][nf >> 1][(nf & 1) * 2 + 1]);
        }
    }

    #pragma unroll
    for (int mf = 0; mf < 4; mf++) {
        const int r0 = m0 + warpM * 64 + mf * 16 + (lane >> 2);
        #pragma unroll
        for (int nf = 0; nf < 8; nf++) {
            const int col = n0 + warpN * 64 + nf * 8 + (lane & 3) * 2;
            const float b0 = bias[col], b1 = bias[col + 1];
            #pragma unroll
            for (int h = 0; h < 2; h++) {
                const int r = r0 + h * 8;
                float v0 = acc[mf][nf][h * 2 + 0] + b0;
                float v1 = acc[mf][nf][h * 2 + 1] + b1;
                if (EPI == 1) {
                    v0 = 0.5f * v0 * (1.0f + erff(v0 * 0.70710678118654752f));
                    v1 = 0.5f * v1 * (1.0f + erff(v1 * 0.70710678118654752f));
                }
                if (EPI == 2) {
                    const float2 rr = *(const float2*)(res + (size_t)r * N + col);
                    v0 += rr.x; v1 += rr.y;
                }
                if (HALF_OUT) {
                    *(__half2*)((__half*)Cv + (size_t)r * N + col) =
                        __floats2half2_rn(v0, v1);
                } else {
                    *(float2*)((float*)Cv + (size_t)r * N + col) =
                        make_float2(v0, v1);
                }
            }
        }
    }
}

// ---------------------------------------------------------------------------
// fp16 tensor-core flash attention with fp16 ACCUMULATION (2x HMMA rate).
// 128 threads, 4 warps x 32 q-rows; register-resident P.
// S accum in f16 is safe: Q pre-scaled by (1/sqrt(768))*log2e -> |S| small.
// O accum in f16: error diluted ~40x through the residual path.
// f16 C-frag (2x half2: row r / row r+8) == A-operand format -> ph unchanged.
// SMEM: Q 16K @0 | K 2x8K @16384 | V 2x8K @32768 = 48KB. 2 CTAs/SM.
// ---------------------------------------------------------------------------
__global__ void __launch_bounds__(128, 2)
attn_kernel(const __half* __restrict__ qkv, __half* __restrict__ out)
{
    extern __shared__ char smem[];
    const uint32_t sb = smem_u32(smem);
    const uint32_t Q0 = 0u, K0 = 16384u, V0 = 32768u;

    const int b  = blockIdx.z;
    const int h  = blockIdx.y;
    const int q0 = blockIdx.x * 128;
    const int tid = threadIdx.x, wid = tid >> 5, lane = tid & 31;

    const float qs = 0.03608439182435162f * 1.4426950408889634f;

    const int krow = tid >> 3;          // 0..15 (+g*16)
    const int kch  = tid & 7;
    const uint32_t kvOff0 = sw128((uint32_t)(krow * 128 + kch * 16));

    // ---- load Q tile 128x64, pre-scaled in fp32 ----
    #pragma unroll
    for (int g = 0; g < 8; g++) {
        const int idx = tid + g * 128;
        const int row = idx >> 3, ch = idx & 7;
        const __half* qp = qkv + (size_t)(b * SEQ + q0 + row) * QKVD + h * HDIM + ch * 8;
        uint4 raw = *(const uint4*)qp;
        __half2* hp = (__half2*)&raw;
        #pragma unroll
        for (int j = 0; j < 4; j++) {
            float2 f = __half22float2(hp[j]);
            hp[j] = __floats2half2_rn(f.x * qs, f.y * qs);
        }
        *(uint4*)(smem + Q0 + sw128((uint32_t)(row * 128 + ch * 16))) = raw;
    }

    // ---- prefetch KV tile 0 ----
    {
        const __half* kp = qkv + (size_t)(b * SEQ + krow) * QKVD + DIM + h * HDIM + kch * 8;
        #pragma unroll
        for (int g = 0; g < 4; g++) {
            const __half* src = kp + (size_t)g * 16 * QKVD;
            CP_ASYNC16(sb + K0 + kvOff0 + g * 2048, src);
            CP_ASYNC16(sb + V0 + kvOff0 + g * 2048, src + DIM);
        }
        CP_COMMIT();
    }

    // ---- fragment offsets (warp owns q-rows [wid*32, wid*32+32)) ----
    uint32_t aOffQ[2], bOffK[4], bOffV[4];
    {
        const int r8 = (lane & 7) + ((lane >> 3) & 1) * 8;
        #pragma unroll
        for (int mf = 0; mf < 2; mf++)
            aOffQ[mf] = sw128((uint32_t)((wid * 32 + mf * 16 + r8) * 128
                                         + (lane >> 4) * 16));
        const int rB = (lane & 7) + ((lane >> 4) & 1) * 8;
        #pragma unroll
        for (int p = 0; p < 4; p++)
            bOffK[p] = sw128((uint32_t)((p * 16 + rB) * 128 + ((lane >> 3) & 1) * 16));
        #pragma unroll
        for (int p = 0; p < 4; p++)
            bOffV[p] = sw128((uint32_t)(r8 * 128 + p * 32 + ((lane >> 4) & 1) * 16));
    }

    // O accumulators in f16 (2 half2 regs per nf: row r, row r+8)
    uint32_t accO[2][8][2];
    #pragma unroll
    for (int i = 0; i < 2; i++)
        #pragma unroll
        for (int j = 0; j < 8; j++) { accO[i][j][0] = 0u; accO[i][j][1] = 0u; }
    float m_i[2][2] = {{-1e30f, -1e30f}, {-1e30f, -1e30f}};
    float l_i[2][2] = {{0.f, 0.f}, {0.f, 0.f}};

    for (int t = 0; t < SEQ / 64; t++) {
        if (t + 1 < SEQ / 64) {
            const uint32_t buf = (uint32_t)((t + 1) & 1) * 8192u;
            const __half* kp = qkv + (size_t)(b * SEQ + (t + 1) * 64 + krow) * QKVD
                               + DIM + h * HDIM + kch * 8;
            #pragma unroll
            for (int g = 0; g < 4; g++) {
                const __half* src = kp + (size_t)g * 16 * QKVD;
                CP_ASYNC16(sb + K0 + buf + kvOff0 + g * 2048, src);
                CP_ASYNC16(sb + V0 + buf + kvOff0 + g * 2048, src + DIM);
            }
        }
        CP_COMMIT();
        CP_WAIT1();
        __syncthreads();

        const uint32_t kB = sb + K0 + (uint32_t)(t & 1) * 8192u;
        const uint32_t vB = sb + V0 + (uint32_t)(t & 1) * 8192u;

        // ---- S = Q K^T, f16 accumulate (2 m-frags x 8 n-frags) ----
        uint32_t accS[2][8][2];
        #pragma unroll
        for (int i = 0; i < 2; i++)
            #pragma unroll
            for (int j = 0; j < 8; j++) { accS[i][j][0] = 0u; accS[i][j][1] = 0u; }

        #pragma unroll
        for (int ds = 0; ds < 4; ds++) {
            const uint32_t kx = (uint32_t)(ds << 5);
            uint32_t aq[2][4], bk[4][4];
            #pragma unroll
            for (int mf = 0; mf < 2; mf++)
                ldsm4(aq[mf], sb + Q0 + (aOffQ[mf] ^ kx));
            #pragma unroll
            for (int p = 0; p < 4; p++)
                ldsm4(bk[p], kB + (bOffK[p] ^ kx));
            #pragma unroll
            for (int mf = 0; mf < 2; mf++)
                #pragma unroll
                for (int nf = 0; nf < 8; nf++)
                    mma_h16(accS[mf][nf], aq[mf],
                            bk[nf >> 1][(nf & 1) * 2],
                            bk[nf >> 1][(nf & 1) * 2 + 1]);
        }

        // ---- online softmax (base 2) in half2 domain, per m-frag ----
        uint32_t ph[2][8][2];
        #pragma unroll
        for (int mf = 0; mf < 2; mf++) {
            __half2 mxh0 = __float2half2_rn(-60000.f);
            __half2 mxh1 = __float2half2_rn(-60000.f);
            #pragma unroll
            for (int nf = 0; nf < 8; nf++) {
                mxh0 = __hmax2(mxh0, *(const __half2*)&accS[mf][nf][0]);
                mxh1 = __hmax2(mxh1, *(const __half2*)&accS[mf][nf][1]);
            }
            float2 fm0 = __half22float2(mxh0);
            float2 fm1 = __half22float2(mxh1);
            float mx0 = fmaxf(fm0.x, fm0.y);
            float mx1 = fmaxf(fm1.x, fm1.y);
            mx0 = fmaxf(mx0, __shfl_xor_sync(0xffffffffu, mx0, 1));
            mx0 = fmaxf(mx0, __shfl_xor_sync(0xffffffffu, mx0, 2));
            mx1 = fmaxf(mx1, __shfl_xor_sync(0xffffffffu, mx1, 1));
            mx1 = fmaxf(mx1, __shfl_xor_sync(0xffffffffu, mx1, 2));

            const float mn0 = fmaxf(m_i[mf][0], mx0), mn1 = fmaxf(m_i[mf][1], mx1);
            const float al0 = fexp2(m_i[mf][0] - mn0), al1 = fexp2(m_i[mf][1] - mn1);
            m_i[mf][0] = mn0;  m_i[mf][1] = mn1;

            const __half2 mn0h = __float2half2_rn(mn0);
            const __half2 mn1h = __float2half2_rn(mn1);
            __half2 sh0 = __float2half2_rn(0.f);
            __half2 sh1 = __float2half2_rn(0.f);
            #pragma unroll
            for (int nf = 0; nf < 8; nf++) {
                __half2 d0 = __hsub2(*(const __half2*)&accS[mf][nf][0], mn0h);
                __half2 d1 = __hsub2(*(const __half2*)&accS[mf][nf][1], mn1h);
                const uint32_t p0 = h2exp2_u(*(const uint32_t*)&d0);
                const uint32_t p1 = h2exp2_u(*(const uint32_t*)&d1);
                ph[mf][nf][0] = p0;  ph[mf][nf][1] = p1;
                sh0 = __hadd2(sh0, *(const __half2*)&p0);
                sh1 = __hadd2(sh1, *(const __half2*)&p1);
            }
            float2 fs0 = __half22float2(sh0);
            float2 fs1 = __half22float2(sh1);
            float s0 = fs0.x + fs0.y;
            float s1 = fs1.x + fs1.y;
            s0 += __shfl_xor_sync(0xffffffffu, s0, 1);
            s0 += __shfl_xor_sync(0xffffffffu, s0, 2);
            s1 += __shfl_xor_sync(0xffffffffu, s1, 1);
            s1 += __shfl_xor_sync(0xffffffffu, s1, 2);
            l_i[mf][0] = l_i[mf][0] * al0 + s0;
            l_i[mf][1] = l_i[mf][1] * al1 + s1;

            const __half2 al0h = __float2half2_rn(al0);
            const __half2 al1h = __float2half2_rn(al1);
            #pragma unroll
            for (int nf = 0; nf < 8; nf++) {
                __half2 o0 = __hmul2(*(const __half2*)&accO[mf][nf][0], al0h);
                __half2 o1 = __hmul2(*(const __half2*)&accO[mf][nf][1], al1h);
                accO[mf][nf][0] = *(const uint32_t*)&o0;
                accO[mf][nf][1] = *(const uint32_t*)&o1;
            }
        }

        // ---- O += P V (f16 accumulate), P from registers ----
        #pragma unroll
        for (int ks = 0; ks < 4; ks++) {
            uint32_t bv[4][4];
            #pragma unroll
            for (int p = 0; p < 4; p++)
                ldsm4t(bv[p], vB + bOffV[p] + (uint32_t)(ks * 2048));
            #pragma unroll
            for (int mf = 0; mf < 2; mf++) {
                uint32_t ap[4] = { ph[mf][2 * ks][0], ph[mf][2 * ks][1],
                                   ph[mf][2 * ks + 1][0], ph[mf][2 * ks + 1][1] };
                #pragma unroll
                for (int nf = 0; nf < 8; nf++)
                    mma_h16(accO[mf][nf], ap,
                            bv[nf >> 1][(nf & 1) * 2],
                            bv[nf >> 1][(nf & 1) * 2 + 1]);
            }
        }
        __syncthreads();   // compute done before next iter's prefetch overwrites
    }

    // ---- normalize + store (half) ----
    #pragma unroll
    for (int mf = 0; mf < 2; mf++) {
        const int r0 = wid * 32 + mf * 16 + (lane >> 2);
        #pragma unroll
        for (int half = 0; half < 2; half++) {
            const int r = r0 + half * 8;
            const float inv = 1.0f / l_i[mf][half];
            __half* op = out + (size_t)(b * SEQ + q0 + r) * DIM + h * HDIM;
            #pragma unroll
            for (int nf = 0; nf < 8; nf++) {
                const float2 o = __half22float2(*(const __half2*)&accO[mf][nf][half]);
                *(__half2*)(op + nf * 8 + (lane & 3) * 2) =
                    __floats2half2_rn(o.x * inv, o.y * inv);
            }
        }
    }
}

// ---------------------------------------------------------------------------
// Host entry
// ---------------------------------------------------------------------------
extern "C" void kernel_launch(void* const* d_in, const int* in_sizes, int n_in,
                              void* d_out, int out_size)
{
    const float* x     = (const float*)d_in[0];
    const float* ln_g  = (const float*)d_in[1];
    const float* ln_b  = (const float*)d_in[2];
    const float* w_qkv = (const float*)d_in[3];
    const float* b_qkv = (const float*)d_in[4];
    const float* w_out = (const float*)d_in[5];
    const float* b_out = (const float*)d_in[6];
    const float* w_fc1 = (const float*)d_in[7];
    const float* b_fc1 = (const float*)d_in[8];
    const float* w_fc2 = (const float*)d_in[9];
    const float* b_fc2 = (const float*)d_in[10];
    float* out = (float*)d_out;

    __half *p_lnh, *p_qkvh, *p_atth, *p_hh;
    __half *p_wqkv, *p_wout, *p_wfc1, *p_wfc2;
    float  *p_x1;
    cudaGetSymbolAddress((void**)&p_lnh,  g_lnh);
    cudaGetSymbolAddress((void**)&p_qkvh, g_qkvh);
    cudaGetSymbolAddress((void**)&p_atth, g_atth);
    cudaGetSymbolAddress((void**)&p_hh,   g_hh);
    cudaGetSymbolAddress((void**)&p_x1,   g_x1);
    cudaGetSymbolAddress((void**)&p_wqkv, g_wqkvh);
    cudaGetSymbolAddress((void**)&p_wout, g_wouth);
    cudaGetSymbolAddress((void**)&p_wfc1, g_wfc1h);
    cudaGetSymbolAddress((void**)&p_wfc2, g_wfc2h);

    const int SMEM_G = 98304;   // GEMM: 3 stages x 32KB
    const int SMEM_A = 49152;   // attn: Q16 + K16 + V16
    cudaFuncSetAttribute(tgemm_kernel<0, true>,
        cudaFuncAttributeMaxDynamicSharedMemorySize, SMEM_G);
    cudaFuncSetAttribute(tgemm_kernel<1, true>,
        cudaFuncAttributeMaxDynamicSharedMemorySize, SMEM_G);
    cudaFuncSetAttribute(tgemm_kernel<2, false>,
        cudaFuncAttributeMaxDynamicSharedMemorySize, SMEM_G);
    cudaFuncSetAttribute(attn_kernel,
        cudaFuncAttributeMaxDynamicSharedMemorySize, SMEM_A);

    // 0) convert all weights to fp16 (single launch)
    const int n0 = QKVD * DIM, n1 = DIM * DIM, n2 = HID * DIM, n3 = DIM * HID;
    const int nAll = n0 + n1 + n2 + n3;
    f2h_all_kernel<<<(nAll / 4 + 255) / 256, 256>>>(
        w_qkv, p_wqkv, n0, w_out, p_wout, n1,
        w_fc1, p_wfc1, n2, w_fc2, p_wfc2, n3);

    // 1) ln1 = LN(x) -> half
    ln_kernel<<<ROWS, 192>>>(x, ln_g, ln_b, p_lnh);

    // 2) qkv = ln1 @ w_qkv^T + b_qkv -> half
    tgemm_kernel<0, true><<<dim3(QKVD / 128, ROWS / 128), 128, SMEM_G>>>(
        p_lnh, p_wqkv, b_qkv, nullptr, p_qkvh, ROWS, QKVD, DIM);

    // 3) fused attention -> half
    attn_kernel<<<dim3(SEQ / 128, HEADS, BATCH), 128, SMEM_A>>>(p_qkvh, p_atth);

    // 4) x1 = x + att @ w_out^T + b_out  (fp32)
    tgemm_kernel<2, false><<<dim3(DIM / 128, ROWS / 128), 128, SMEM_G>>>(
        p_atth, p_wout, b_out, x, p_x1, ROWS, DIM, DIM);

    // 5) ln2 = LN(x1) -> half
    ln_kernel<<<ROWS, 192>>>(p_x1, ln_g, ln_b, p_lnh);

    // 6) h = gelu(ln2 @ w_fc1^T + b_fc1) -> half
    tgemm_kernel<1, true><<<dim3(HID / 128, ROWS / 128), 128, SMEM_G>>>(
        p_lnh, p_wfc1, b_fc1, nullptr, p_hh, ROWS, HID, DIM);

    // 7) out = x1 + h @ w_fc2^T + b_fc2  (fp32)
    tgemm_kernel<2, false><<<dim3(DIM / 128, ROWS / 128), 128, SMEM_G>>>(
        p_hh, p_wfc2, b_fc2, p_x1, out, ROWS, DIM, HID);
}

// round 17
// speedup vs baseline: 1.0677x; 1.0109x over previous
#include <cuda_runtime.h>
#include <cuda_fp16.h>
#include <cstdint>
#include <math.h>

// ---------------------------------------------------------------------------
// Problem constants
// ---------------------------------------------------------------------------
#define BATCH 16
#define SEQ   1024
#define DIM   768
#define HEADS 12
#define HDIM  64
#define HID   3072
#define ROWS  (BATCH*SEQ)     // 16384
#define QKVD  (3*DIM)         // 2304

// ---------------------------------------------------------------------------
// Scratch (device globals — no allocation allowed)
// ---------------------------------------------------------------------------
__device__ __half g_lnh [(size_t)ROWS * DIM];
__device__ __half g_qkvh[(size_t)ROWS * QKVD];
__device__ __half g_atth[(size_t)ROWS * DIM];
__device__ __half g_hh  [(size_t)ROWS * HID];
__device__ float  g_x1  [(size_t)ROWS * DIM];
__device__ __half g_wqkvh[(size_t)QKVD * DIM];
__device__ __half g_wouth[(size_t)DIM * DIM];
__device__ __half g_wfc1h[(size_t)HID * DIM];
__device__ __half g_wfc2h[(size_t)DIM * HID];

// ---------------------------------------------------------------------------
// Helpers
// ---------------------------------------------------------------------------
__device__ __forceinline__ uint32_t smem_u32(const void* p) {
    uint32_t a;
    asm("{ .reg .u64 t; cvta.to.shared.u64 t, %1; cvt.u32.u64 %0, t; }" : "=r"(a) : "l"(p));
    return a;
}
__device__ __forceinline__ void ldsm4(uint32_t* r, uint32_t addr) {
    asm volatile("ldmatrix.sync.aligned.m8n8.x4.shared.b16 {%0,%1,%2,%3}, [%4];"
        : "=r"(r[0]), "=r"(r[1]), "=r"(r[2]), "=r"(r[3]) : "r"(addr));
}
__device__ __forceinline__ void ldsm4t(uint32_t* r, uint32_t addr) {
    asm volatile("ldmatrix.sync.aligned.m8n8.x4.trans.shared.b16 {%0,%1,%2,%3}, [%4];"
        : "=r"(r[0]), "=r"(r[1]), "=r"(r[2]), "=r"(r[3]) : "r"(addr));
}
__device__ __forceinline__ void mma_f16(float* c, const uint32_t* a,
                                        uint32_t b0, uint32_t b1) {
    asm volatile(
        "mma.sync.aligned.m16n8k16.row.col.f32.f16.f16.f32 "
        "{%0,%1,%2,%3}, {%4,%5,%6,%7}, {%8,%9}, {%0,%1,%2,%3};"
        : "+f"(c[0]), "+f"(c[1]), "+f"(c[2]), "+f"(c[3])
        : "r"(a[0]), "r"(a[1]), "r"(a[2]), "r"(a[3]), "r"(b0), "r"(b1));
}
// fp16-accumulate variant: C/D = 2 regs (half2 x2: row r, row r+8)
__device__ __forceinline__ void mma_h16(uint32_t* c, const uint32_t* a,
                                        uint32_t b0, uint32_t b1) {
    asm volatile(
        "mma.sync.aligned.m16n8k16.row.col.f16.f16.f16.f16 "
        "{%0,%1}, {%2,%3,%4,%5}, {%6,%7}, {%0,%1};"
        : "+r"(c[0]), "+r"(c[1])
        : "r"(a[0]), "r"(a[1]), "r"(a[2]), "r"(a[3]), "r"(b0), "r"(b1));
}
__device__ __forceinline__ uint32_t sw128(uint32_t off) {
    return off ^ ((off >> 3) & 0x70);
}
__device__ __forceinline__ float fexp2(float x) {
    float y; asm("ex2.approx.f32 %0, %1;" : "=f"(y) : "f"(x)); return y;
}
__device__ __forceinline__ uint32_t h2exp2_u(uint32_t x) {
    uint32_t y; asm("ex2.approx.f16x2 %0, %1;" : "=r"(y) : "r"(x)); return y;
}
#define CP_ASYNC16(dst, src) \
    asm volatile("cp.async.cg.shared.global [%0], [%1], 16;" \
                 :: "r"(dst), "l"(src) : "memory")
#define CP_COMMIT() asm volatile("cp.async.commit_group;" ::: "memory")
#define CP_WAIT1()  asm volatile("cp.async.wait_group 1;"  ::: "memory")

// ---------------------------------------------------------------------------
// fp32 -> fp16 conversion, all four weights in one launch
// ---------------------------------------------------------------------------
__global__ void f2h_all_kernel(const float* __restrict__ s0, __half* __restrict__ d0, int n0,
                               const float* __restrict__ s1, __half* __restrict__ d1, int n1,
                               const float* __restrict__ s2, __half* __restrict__ d2, int n2,
                               const float* __restrict__ s3, __half* __restrict__ d3, int n3)
{
    int i = (blockIdx.x * 256 + threadIdx.x) * 4;
    const float* s; __half* d;
    if (i < n0)                   { s = s0; d = d0; }
    else if ((i -= n0) < n1)      { s = s1; d = d1; }
    else if ((i -= n1) < n2)      { s = s2; d = d2; }
    else if ((i -= n2) < n3)      { s = s3; d = d3; }
    else return;
    float4 v = *(const float4*)(s + i);
    *(__half2*)(d + i)     = __floats2half2_rn(v.x, v.y);
    *(__half2*)(d + i + 2) = __floats2half2_rn(v.z, v.w);
}

// ---------------------------------------------------------------------------
// LayerNorm: warp-per-row (D=768 = 6 float4 per lane), shfl-only reduction,
// no smem, no __syncthreads. 256 threads = 8 rows/block, grid = ROWS/8.
// ---------------------------------------------------------------------------
__global__ void __launch_bounds__(256)
ln_kernel(const float* __restrict__ x,
          const float* __restrict__ gg,
          const float* __restrict__ bb,
          __half* __restrict__ y)
{
    const int row  = blockIdx.x * 8 + (threadIdx.x >> 5);
    const int lane = threadIdx.x & 31;
    const float4* xr = (const float4*)(x + (size_t)row * DIM);

    float4 v[6];
    float s = 0.f, q = 0.f;
    #pragma unroll
    for (int j = 0; j < 6; j++) {
        v[j] = xr[lane + 32 * j];
        s += v[j].x + v[j].y + v[j].z + v[j].w;
        q += v[j].x*v[j].x + v[j].y*v[j].y + v[j].z*v[j].z + v[j].w*v[j].w;
    }
    #pragma unroll
    for (int m = 16; m; m >>= 1) {
        s += __shfl_xor_sync(0xffffffffu, s, m);
        q += __shfl_xor_sync(0xffffffffu, q, m);
    }
    const float mean = s * (1.0f / DIM);
    const float rstd = rsqrtf(q * (1.0f / DIM) - mean * mean + 1e-5f);

    __half* yr = y + (size_t)row * DIM;
    #pragma unroll
    for (int j = 0; j < 6; j++) {
        const int c = (lane + 32 * j) * 4;
        const float4 g4 = *(const float4*)(gg + c);
        const float4 b4 = *(const float4*)(bb + c);
        __half2 h0 = __floats2half2_rn((v[j].x - mean) * rstd * g4.x + b4.x,
                                       (v[j].y - mean) * rstd * g4.y + b4.y);
        __half2 h1 = __floats2half2_rn((v[j].z - mean) * rstd * g4.z + b4.z,
                                       (v[j].w - mean) * rstd * g4.w + b4.w);
        *(__half2*)(yr + c)     = h0;
        *(__half2*)(yr + c + 2) = h1;
    }
}

// ---------------------------------------------------------------------------
// fp16 mma.sync GEMM (R15 config, frozen).
// CTA tile 128x128, BK=64. 4 warps (2M x 2N), warp tile 64x64.
// 128 threads, __launch_bounds__(128,2); SMEM 3 x 32KB; f32 accumulate.
// EPI: 0 = bias, 1 = bias+GELU(exact), 2 = bias+residual(fp32)
// ---------------------------------------------------------------------------
template<int EPI, bool HALF_OUT>
__global__ void __launch_bounds__(128, 2)
tgemm_kernel(const __half* __restrict__ A,
             const __half* __restrict__ W,
             const float* __restrict__ bias,
             const float* __restrict__ res,
             void* __restrict__ Cv,
             int M, int N, int K)
{
    extern __shared__ char smem[];
    const uint32_t sb = smem_u32(smem);
    const int tid   = threadIdx.x;
    const int wid   = tid >> 5;
    const int lane  = tid & 31;
    const int warpM = wid & 1;
    const int warpN = wid >> 1;
    const int m0 = blockIdx.y * 128;
    const int n0 = blockIdx.x * 128;

    uint32_t aOff[4], bOff[4];
    {
        const int r8 = (lane & 7) + ((lane >> 3) & 1) * 8;
        #pragma unroll
        for (int mf = 0; mf < 4; mf++) {
            const int row = warpM * 64 + mf * 16 + r8;
            aOff[mf] = sw128((uint32_t)(row * 128 + (lane >> 4) * 16));
        }
        const int rB = (lane & 7) + ((lane >> 4) & 1) * 8;
        #pragma unroll
        for (int p = 0; p < 4; p++) {
            const int row = warpN * 64 + p * 16 + rB;
            bOff[p] = sw128((uint32_t)(row * 128 + ((lane >> 3) & 1) * 16));
        }
    }

    float acc[4][8][4];
    #pragma unroll
    for (int i = 0; i < 4; i++)
        #pragma unroll
        for (int j = 0; j < 8; j++)
            #pragma unroll
            for (int q = 0; q < 4; q++) acc[i][j][q] = 0.f;

    const int nIter = K >> 6;                 // BK = 64 halfs
    const int lr0  = tid >> 3;
    const int lch  = tid & 7;
    const uint32_t stOff = sw128((uint32_t)(lr0 * 128 + lch * 16));
    const __half* apt = A + (size_t)(m0 + lr0) * K + lch * 8;
    const __half* bpt = W + (size_t)(n0 + lr0) * K + lch * 8;

    #pragma unroll
    for (int s = 0; s < 2; s++) {
        const int k0 = s << 6;
        const uint32_t dstA = sb + (uint32_t)s * 32768u + stOff;
        #pragma unroll
        for (int g = 0; g < 8; g++)
            CP_ASYNC16(dstA + g * 2048, apt + (size_t)g * 16 * K + k0);
        #pragma unroll
        for (int g = 0; g < 8; g++)
            CP_ASYNC16(dstA + 16384 + g * 2048, bpt + (size_t)g * 16 * K + k0);
        CP_COMMIT();
    }

    int slotNext = 2;
    for (int it = 0; it < nIter; ++it) {
        CP_WAIT1();
        __syncthreads();

        if (it + 2 < nIter) {
            const int k0 = (it + 2) << 6;
            const uint32_t dstA = sb + (uint32_t)slotNext * 32768u + stOff;
            #pragma unroll
            for (int g = 0; g < 8; g++)
                CP_ASYNC16(dstA + g * 2048, apt + (size_t)g * 16 * K + k0);
            #pragma unroll
            for (int g = 0; g < 8; g++)
                CP_ASYNC16(dstA + 16384 + g * 2048, bpt + (size_t)g * 16 * K + k0);
        }
        CP_COMMIT();
        slotNext = (slotNext == 2) ? 0 : slotNext + 1;

        const uint32_t aB = sb + (uint32_t)(it % 3) * 32768u;
        const uint32_t bB = aB + 16384u;

        // ks-level double-buffered fragments
        uint32_t af[2][4][4], bf[2][4][4];
        #pragma unroll
        for (int mf = 0; mf < 4; mf++) ldsm4(af[0][mf], aB + aOff[mf]);
        #pragma unroll
        for (int p = 0; p < 4; p++)   ldsm4(bf[0][p],  bB + bOff[p]);

        #pragma unroll
        for (int ks = 0; ks < 4; ks++) {
            const int cur = ks & 1, nxt = cur ^ 1;
            if (ks < 3) {
                const uint32_t kx = (uint32_t)((ks + 1) << 5);
                #pragma unroll
                for (int mf = 0; mf < 4; mf++)
                    ldsm4(af[nxt][mf], aB + (aOff[mf] ^ kx));
                #pragma unroll
                for (int p = 0; p < 4; p++)
                    ldsm4(bf[nxt][p],  bB + (bOff[p]  ^ kx));
            }
            #pragma unroll
            for (int mf = 0; mf < 4; mf++)
                #pragma unroll
                for (int nf = 0; nf < 8; nf++)
                    mma_f16(acc[mf][nf], af[cur][mf],
                            bf[cur][nf >> 1][(nf & 1) * 2],
                            bf[cur][nf >> 1][(nf & 1) * 2 + 1]);
        }
    }

    #pragma unroll
    for (int mf = 0; mf < 4; mf++) {
        const int r0 = m0 + warpM * 64 + mf * 16 + (lane >> 2);
        #pragma unroll
        for (int nf = 0; nf < 8; nf++) {
            const int col = n0 + warpN * 64 + nf * 8 + (lane & 3) * 2;
            const float b0 = bias[col], b1 = bias[col + 1];
            #pragma unroll
            for (int h = 0; h < 2; h++) {
                const int r = r0 + h * 8;
                float v0 = acc[mf][nf][h * 2 + 0] + b0;
                float v1 = acc[mf][nf][h * 2 + 1] + b1;
                if (EPI == 1) {
                    v0 = 0.5f * v0 * (1.0f + erff(v0 * 0.70710678118654752f));
                    v1 = 0.5f * v1 * (1.0f + erff(v1 * 0.70710678118654752f));
                }
                if (EPI == 2) {
                    const float2 rr = *(const float2*)(res + (size_t)r * N + col);
                    v0 += rr.x; v1 += rr.y;
                }
                if (HALF_OUT) {
                    *(__half2*)((__half*)Cv + (size_t)r * N + col) =
                        __floats2half2_rn(v0, v1);
                } else {
                    *(float2*)((float*)Cv + (size_t)r * N + col) =
                        make_float2(v0, v1);
                }
            }
        }
    }
}

// ---------------------------------------------------------------------------
// fp16 tensor-core flash attention, fp16 accumulation (R16), now 3 CTAs/SM.
// 128 threads, 4 warps x 32 q-rows; register-resident P; base-2 softmax.
// SMEM: Q 16K @0 | K 2x8K @16384 | V 2x8K @32768 = 48KB. 3 CTAs/SM (144KB).
// ---------------------------------------------------------------------------
__global__ void __launch_bounds__(128, 3)
attn_kernel(const __half* __restrict__ qkv, __half* __restrict__ out)
{
    extern __shared__ char smem[];
    const uint32_t sb = smem_u32(smem);
    const uint32_t Q0 = 0u, K0 = 16384u, V0 = 32768u;

    const int b  = blockIdx.z;
    const int h  = blockIdx.y;
    const int q0 = blockIdx.x * 128;
    const int tid = threadIdx.x, wid = tid >> 5, lane = tid & 31;

    const float qs = 0.03608439182435162f * 1.4426950408889634f;

    const int krow = tid >> 3;          // 0..15 (+g*16)
    const int kch  = tid & 7;
    const uint32_t kvOff0 = sw128((uint32_t)(krow * 128 + kch * 16));

    // ---- load Q tile 128x64, pre-scaled in fp32 ----
    #pragma unroll
    for (int g = 0; g < 8; g++) {
        const int idx = tid + g * 128;
        const int row = idx >> 3, ch = idx & 7;
        const __half* qp = qkv + (size_t)(b * SEQ + q0 + row) * QKVD + h * HDIM + ch * 8;
        uint4 raw = *(const uint4*)qp;
        __half2* hp = (__half2*)&raw;
        #pragma unroll
        for (int j = 0; j < 4; j++) {
            float2 f = __half22float2(hp[j]);
            hp[j] = __floats2half2_rn(f.x * qs, f.y * qs);
        }
        *(uint4*)(smem + Q0 + sw128((uint32_t)(row * 128 + ch * 16))) = raw;
    }

    // ---- prefetch KV tile 0 ----
    {
        const __half* kp = qkv + (size_t)(b * SEQ + krow) * QKVD + DIM + h * HDIM + kch * 8;
        #pragma unroll
        for (int g = 0; g < 4; g++) {
            const __half* src = kp + (size_t)g * 16 * QKVD;
            CP_ASYNC16(sb + K0 + kvOff0 + g * 2048, src);
            CP_ASYNC16(sb + V0 + kvOff0 + g * 2048, src + DIM);
        }
        CP_COMMIT();
    }

    // ---- fragment offsets (warp owns q-rows [wid*32, wid*32+32)) ----
    uint32_t aOffQ[2], bOffK[4], bOffV[4];
    {
        const int r8 = (lane & 7) + ((lane >> 3) & 1) * 8;
        #pragma unroll
        for (int mf = 0; mf < 2; mf++)
            aOffQ[mf] = sw128((uint32_t)((wid * 32 + mf * 16 + r8) * 128
                                         + (lane >> 4) * 16));
        const int rB = (lane & 7) + ((lane >> 4) & 1) * 8;
        #pragma unroll
        for (int p = 0; p < 4; p++)
            bOffK[p] = sw128((uint32_t)((p * 16 + rB) * 128 + ((lane >> 3) & 1) * 16));
        #pragma unroll
        for (int p = 0; p < 4; p++)
            bOffV[p] = sw128((uint32_t)(r8 * 128 + p * 32 + ((lane >> 4) & 1) * 16));
    }

    // O accumulators in f16 (2 half2 regs per nf: row r, row r+8)
    uint32_t accO[2][8][2];
    #pragma unroll
    for (int i = 0; i < 2; i++)
        #pragma unroll
        for (int j = 0; j < 8; j++) { accO[i][j][0] = 0u; accO[i][j][1] = 0u; }
    float m_i[2][2] = {{-1e30f, -1e30f}, {-1e30f, -1e30f}};
    float l_i[2][2] = {{0.f, 0.f}, {0.f, 0.f}};

    for (int t = 0; t < SEQ / 64; t++) {
        if (t + 1 < SEQ / 64) {
            const uint32_t buf = (uint32_t)((t + 1) & 1) * 8192u;
            const __half* kp = qkv + (size_t)(b * SEQ + (t + 1) * 64 + krow) * QKVD
                               + DIM + h * HDIM + kch * 8;
            #pragma unroll
            for (int g = 0; g < 4; g++) {
                const __half* src = kp + (size_t)g * 16 * QKVD;
                CP_ASYNC16(sb + K0 + buf + kvOff0 + g * 2048, src);
                CP_ASYNC16(sb + V0 + buf + kvOff0 + g * 2048, src + DIM);
            }
        }
        CP_COMMIT();
        CP_WAIT1();
        __syncthreads();

        const uint32_t kB = sb + K0 + (uint32_t)(t & 1) * 8192u;
        const uint32_t vB = sb + V0 + (uint32_t)(t & 1) * 8192u;

        // ---- S = Q K^T, f16 accumulate (2 m-frags x 8 n-frags) ----
        uint32_t accS[2][8][2];
        #pragma unroll
        for (int i = 0; i < 2; i++)
            #pragma unroll
            for (int j = 0; j < 8; j++) { accS[i][j][0] = 0u; accS[i][j][1] = 0u; }

        #pragma unroll
        for (int ds = 0; ds < 4; ds++) {
            const uint32_t kx = (uint32_t)(ds << 5);
            uint32_t aq[2][4], bk[4][4];
            #pragma unroll
            for (int mf = 0; mf < 2; mf++)
                ldsm4(aq[mf], sb + Q0 + (aOffQ[mf] ^ kx));
            #pragma unroll
            for (int p = 0; p < 4; p++)
                ldsm4(bk[p], kB + (bOffK[p] ^ kx));
            #pragma unroll
            for (int mf = 0; mf < 2; mf++)
                #pragma unroll
                for (int nf = 0; nf < 8; nf++)
                    mma_h16(accS[mf][nf], aq[mf],
                            bk[nf >> 1][(nf & 1) * 2],
                            bk[nf >> 1][(nf & 1) * 2 + 1]);
        }

        // ---- online softmax (base 2) in half2 domain, per m-frag ----
        uint32_t ph[2][8][2];
        #pragma unroll
        for (int mf = 0; mf < 2; mf++) {
            __half2 mxh0 = __float2half2_rn(-60000.f);
            __half2 mxh1 = __float2half2_rn(-60000.f);
            #pragma unroll
            for (int nf = 0; nf < 8; nf++) {
                mxh0 = __hmax2(mxh0, *(const __half2*)&accS[mf][nf][0]);
                mxh1 = __hmax2(mxh1, *(const __half2*)&accS[mf][nf][1]);
            }
            float2 fm0 = __half22float2(mxh0);
            float2 fm1 = __half22float2(mxh1);
            float mx0 = fmaxf(fm0.x, fm0.y);
            float mx1 = fmaxf(fm1.x, fm1.y);
            mx0 = fmaxf(mx0, __shfl_xor_sync(0xffffffffu, mx0, 1));
            mx0 = fmaxf(mx0, __shfl_xor_sync(0xffffffffu, mx0, 2));
            mx1 = fmaxf(mx1, __shfl_xor_sync(0xffffffffu, mx1, 1));
            mx1 = fmaxf(mx1, __shfl_xor_sync(0xffffffffu, mx1, 2));

            const float mn0 = fmaxf(m_i[mf][0], mx0), mn1 = fmaxf(m_i[mf][1], mx1);
            const float al0 = fexp2(m_i[mf][0] - mn0), al1 = fexp2(m_i[mf][1] - mn1);
            m_i[mf][0] = mn0;  m_i[mf][1] = mn1;

            const __half2 mn0h = __float2half2_rn(mn0);
            const __half2 mn1h = __float2half2_rn(mn1);
            __half2 sh0 = __float2half2_rn(0.f);
            __half2 sh1 = __float2half2_rn(0.f);
            #pragma unroll
            for (int nf = 0; nf < 8; nf++) {
                __half2 d0 = __hsub2(*(const __half2*)&accS[mf][nf][0], mn0h);
                __half2 d1 = __hsub2(*(const __half2*)&accS[mf][nf][1], mn1h);
                const uint32_t p0 = h2exp2_u(*(const uint32_t*)&d0);
                const uint32_t p1 = h2exp2_u(*(const uint32_t*)&d1);
                ph[mf][nf][0] = p0;  ph[mf][nf][1] = p1;
                sh0 = __hadd2(sh0, *(const __half2*)&p0);
                sh1 = __hadd2(sh1, *(const __half2*)&p1);
            }
            float2 fs0 = __half22float2(sh0);
            float2 fs1 = __half22float2(sh1);
            float s0 = fs0.x + fs0.y;
            float s1 = fs1.x + fs1.y;
            s0 += __shfl_xor_sync(0xffffffffu, s0, 1);
            s0 += __shfl_xor_sync(0xffffffffu, s0, 2);
            s1 += __shfl_xor_sync(0xffffffffu, s1, 1);
            s1 += __shfl_xor_sync(0xffffffffu, s1, 2);
            l_i[mf][0] = l_i[mf][0] * al0 + s0;
            l_i[mf][1] = l_i[mf][1] * al1 + s1;

            const __half2 al0h = __float2half2_rn(al0);
            const __half2 al1h = __float2half2_rn(al1);
            #pragma unroll
            for (int nf = 0; nf < 8; nf++) {
                __half2 o0 = __hmul2(*(const __half2*)&accO[mf][nf][0], al0h);
                __half2 o1 = __hmul2(*(const __half2*)&accO[mf][nf][1], al1h);
                accO[mf][nf][0] = *(const uint32_t*)&o0;
                accO[mf][nf][1] = *(const uint32_t*)&o1;
            }
        }

        // ---- O += P V (f16 accumulate), P from registers ----
        #pragma unroll
        for (int ks = 0; ks < 4; ks++) {
            uint32_t bv[4][4];
            #pragma unroll
            for (int p = 0; p < 4; p++)
                ldsm4t(bv[p], vB + bOffV[p] + (uint32_t)(ks * 2048));
            #pragma unroll
            for (int mf = 0; mf < 2; mf++) {
                uint32_t ap[4] = { ph[mf][2 * ks][0], ph[mf][2 * ks][1],
                                   ph[mf][2 * ks + 1][0], ph[mf][2 * ks + 1][1] };
                #pragma unroll
                for (int nf = 0; nf < 8; nf++)
                    mma_h16(accO[mf][nf], ap,
                            bv[nf >> 1][(nf & 1) * 2],
                            bv[nf >> 1][(nf & 1) * 2 + 1]);
            }
        }
        __syncthreads();   // compute done before next iter's prefetch overwrites
    }

    // ---- normalize + store (half) ----
    #pragma unroll
    for (int mf = 0; mf < 2; mf++) {
        const int r0 = wid * 32 + mf * 16 + (lane >> 2);
        #pragma unroll
        for (int half = 0; half < 2; half++) {
            const int r = r0 + half * 8;
            const float inv = 1.0f / l_i[mf][half];
            __half* op = out + (size_t)(b * SEQ + q0 + r) * DIM + h * HDIM;
            #pragma unroll
            for (int nf = 0; nf < 8; nf++) {
                const float2 o = __half22float2(*(const __half2*)&accO[mf][nf][half]);
                *(__half2*)(op + nf * 8 + (lane & 3) * 2) =
                    __floats2half2_rn(o.x * inv, o.y * inv);
            }
        }
    }
}

// ---------------------------------------------------------------------------
// Host entry
// ---------------------------------------------------------------------------
extern "C" void kernel_launch(void* const* d_in, const int* in_sizes, int n_in,
                              void* d_out, int out_size)
{
    const float* x     = (const float*)d_in[0];
    const float* ln_g  = (const float*)d_in[1];
    const float* ln_b  = (const float*)d_in[2];
    const float* w_qkv = (const float*)d_in[3];
    const float* b_qkv = (const float*)d_in[4];
    const float* w_out = (const float*)d_in[5];
    const float* b_out = (const float*)d_in[6];
    const float* w_fc1 = (const float*)d_in[7];
    const float* b_fc1 = (const float*)d_in[8];
    const float* w_fc2 = (const float*)d_in[9];
    const float* b_fc2 = (const float*)d_in[10];
    float* out = (float*)d_out;

    __half *p_lnh, *p_qkvh, *p_atth, *p_hh;
    __half *p_wqkv, *p_wout, *p_wfc1, *p_wfc2;
    float  *p_x1;
    cudaGetSymbolAddress((void**)&p_lnh,  g_lnh);
    cudaGetSymbolAddress((void**)&p_qkvh, g_qkvh);
    cudaGetSymbolAddress((void**)&p_atth, g_atth);
    cudaGetSymbolAddress((void**)&p_hh,   g_hh);
    cudaGetSymbolAddress((void**)&p_x1,   g_x1);
    cudaGetSymbolAddress((void**)&p_wqkv, g_wqkvh);
    cudaGetSymbolAddress((void**)&p_wout, g_wouth);
    cudaGetSymbolAddress((void**)&p_wfc1, g_wfc1h);
    cudaGetSymbolAddress((void**)&p_wfc2, g_wfc2h);

    const int SMEM_G = 98304;   // GEMM: 3 stages x 32KB
    const int SMEM_A = 49152;   // attn: Q16 + K16 + V16
    cudaFuncSetAttribute(tgemm_kernel<0, true>,
        cudaFuncAttributeMaxDynamicSharedMemorySize, SMEM_G);
    cudaFuncSetAttribute(tgemm_kernel<1, true>,
        cudaFuncAttributeMaxDynamicSharedMemorySize, SMEM_G);
    cudaFuncSetAttribute(tgemm_kernel<2, false>,
        cudaFuncAttributeMaxDynamicSharedMemorySize, SMEM_G);
    cudaFuncSetAttribute(attn_kernel,
        cudaFuncAttributeMaxDynamicSharedMemorySize, SMEM_A);

    // 0) convert all weights to fp16 (single launch)
    const int n0 = QKVD * DIM, n1 = DIM * DIM, n2 = HID * DIM, n3 = DIM * HID;
    const int nAll = n0 + n1 + n2 + n3;
    f2h_all_kernel<<<(nAll / 4 + 255) / 256, 256>>>(
        w_qkv, p_wqkv, n0, w_out, p_wout, n1,
        w_fc1, p_wfc1, n2, w_fc2, p_wfc2, n3);

    // 1) ln1 = LN(x) -> half
    ln_kernel<<<ROWS / 8, 256>>>(x, ln_g, ln_b, p_lnh);

    // 2) qkv = ln1 @ w_qkv^T + b_qkv -> half
    tgemm_kernel<0, true><<<dim3(QKVD / 128, ROWS / 128), 128, SMEM_G>>>(
        p_lnh, p_wqkv, b_qkv, nullptr, p_qkvh, ROWS, QKVD, DIM);

    // 3) fused attention -> half
    attn_kernel<<<dim3(SEQ / 128, HEADS, BATCH), 128, SMEM_A>>>(p_qkvh, p_atth);

    // 4) x1 = x + att @ w_out^T + b_out  (fp32)
    tgemm_kernel<2, false><<<dim3(DIM / 128, ROWS / 128), 128, SMEM_G>>>(
        p_atth, p_wout, b_out, x, p_x1, ROWS, DIM, DIM);

    // 5) ln2 = LN(x1) -> half
    ln_kernel<<<ROWS / 8, 256>>>(p_x1, ln_g, ln_b, p_lnh);

    // 6) h = gelu(ln2 @ w_fc1^T + b_fc1) -> half
    tgemm_kernel<1, true><<<dim3(HID / 128, ROWS / 128), 128, SMEM_G>>>(
        p_lnh, p_wfc1, b_fc1, nullptr, p_hh, ROWS, HID, DIM);

    // 7) out = x1 + h @ w_fc2^T + b_fc2  (fp32)
    tgemm_kernel<2, false><<<dim3(DIM / 128, ROWS / 128), 128, SMEM_G>>>(
        p_hh, p_wfc2, b_fc2, p_x1, out, ROWS, DIM, HID);
}